// round 14
// baseline (speedup 1.0000x reference)
#include <cuda_runtime.h>
#include <cuda_fp16.h>
#include <math.h>
#include <stdint.h>
#include <mma.h>

using namespace nvcuda;

#define BDIM   32
#define TENC   1024
#define TDEC   2048
#define DMODEL 256
#define INDIM  80
#define C2     512
#define MTOT   (BDIM*TDEC)
#define RSQRT2 0.70710678118654752440f

typedef unsigned long long u64;

// ---------------- scratch ----------------
__device__ float  g_X [(size_t)MTOT*DMODEL];
__device__ float  g_H0[(size_t)MTOT*DMODEL];
__device__ float  g_H1[(size_t)MTOT*DMODEL];
__device__ __half g_XH[(size_t)MTOT*DMODEL];
__device__ __half g_H0h[(size_t)MTOT*DMODEL];
__device__ __half g_H0l[(size_t)MTOT*DMODEL];
__device__ __half g_Qh[(size_t)MTOT*DMODEL];
__device__ __half g_Ql[(size_t)MTOT*DMODEL];
__device__ float  g_S [(size_t)BDIM*TDEC*TENC];
__device__ __half g_AHh[(size_t)BDIM*TDEC*TENC];
__device__ __half g_AHl[(size_t)BDIM*TDEC*TENC];
__device__ __half g_EHh[(size_t)BDIM*TENC*DMODEL];
__device__ __half g_EHl[(size_t)BDIM*TENC*DMODEL];
__device__ __half g_VHh[(size_t)BDIM*TENC*DMODEL];
__device__ __half g_VHl[(size_t)BDIM*TENC*DMODEL];
__device__ __half g_WbH0[(size_t)C2*1280];
__device__ __half g_WbH1[(size_t)C2*1280];
__device__ __half g_WAh[(size_t)DMODEL*DMODEL];
__device__ __half g_WAl[(size_t)DMODEL*DMODEL];
__device__ __half g_WPh[(size_t)INDIM*DMODEL];
__device__ __half g_WPl[(size_t)INDIM*DMODEL];

__device__ __forceinline__ float sigf(float x) { return 1.0f / (1.0f + __expf(-x)); }
__device__ __forceinline__ void split_h(float x, __half &hi, __half &lo) {
    hi = __float2half_rn(x);
    lo = __float2half_rn(x - __half2float(hi));
}

// ---------------- weight repack + fp16 round ----------------
__global__ void __launch_bounds__(256) k_repack_nk(const float* __restrict__ w,
                                                   __half* __restrict__ wb)
{
    int i = blockIdx.x * 256 + threadIdx.x;
    if (i >= C2 * DMODEL * 5) return;
    int n   = i / (DMODEL * 5);
    int rem = i - n * (DMODEL * 5);
    int ch  = rem / 5;
    int tap = rem - ch * 5;
    wb[(size_t)n * 1280 + tap * DMODEL + ch] = __float2half_rn(w[i]);
}

// ---------------- enc/V prep ----------------
__global__ void __launch_bounds__(256) k_prep_enc(
    const float* __restrict__ enc, const float* __restrict__ first,
    __half* __restrict__ Eh, __half* __restrict__ El,
    __half* __restrict__ Vh, __half* __restrict__ Vl)
{
    size_t i = (size_t)blockIdx.x * 256 + threadIdx.x;
    float4 e = *(const float4*)(enc + i * 4);
    float4 f = *(const float4*)(first + i * 4);
    __half eh[4], el[4], vh[4], vl[4];
    split_h(e.x, eh[0], el[0]); split_h(e.y, eh[1], el[1]);
    split_h(e.z, eh[2], el[2]); split_h(e.w, eh[3], el[3]);
    split_h(e.x + f.x, vh[0], vl[0]); split_h(e.y + f.y, vh[1], vl[1]);
    split_h(e.z + f.z, vh[2], vl[2]); split_h(e.w + f.w, vh[3], vl[3]);
    *(ulonglong1*)(Eh + i * 4) = *(ulonglong1*)eh;
    *(ulonglong1*)(El + i * 4) = *(ulonglong1*)el;
    *(ulonglong1*)(Vh + i * 4) = *(ulonglong1*)vh;
    *(ulonglong1*)(Vl + i * 4) = *(ulonglong1*)vl;
}

// ---------------- fp32 -> hi/lo split (weights only) ----------------
__global__ void __launch_bounds__(256) k_split(
    const float* __restrict__ x, __half* __restrict__ hi, __half* __restrict__ lo)
{
    size_t i = (size_t)blockIdx.x * 256 + threadIdx.x;
    float4 v = *(const float4*)(x + i * 4);
    __half h[4], l[4];
    split_h(v.x, h[0], l[0]); split_h(v.y, h[1], l[1]);
    split_h(v.z, h[2], l[2]); split_h(v.w, h[3], l[3]);
    *(ulonglong1*)(hi + i * 4) = *(ulonglong1*)h;
    *(ulonglong1*)(lo + i * 4) = *(ulonglong1*)l;
}

// ================= conv: fp16 wmma single-buffer, K-chunk=64 (R12-proven) =================
#define CPADH 72
#define SMH   (256*CPADH)
#define EPAD  68
__global__ void __launch_bounds__(256, 2) k_conv_wmma(
    const float* __restrict__ Xres, const __half* __restrict__ XH,
    const __half* __restrict__ Wb, const float* __restrict__ bias,
    float* __restrict__ out, __half* __restrict__ outH, __half* __restrict__ outL)
{
    extern __shared__ __align__(16) __half smh[];
    __half* As = smh;
    __half* Bh = smh + 128 * CPADH;
    const int tid = threadIdx.x;
    const int wid = tid >> 5;
    const int m0 = blockIdx.x * 128;
    const int n0 = blockIdx.y * 64;
    const int wm = wid & 3;
    const int wn = wid >> 2;

    wmma::fragment<wmma::accumulator, 16, 16, 16, float> Ca[2][2], Cg[2][2];
    #pragma unroll
    for (int i = 0; i < 2; ++i)
        #pragma unroll
        for (int j = 0; j < 2; ++j) {
            wmma::fill_fragment(Ca[i][j], 0.0f);
            wmma::fill_fragment(Cg[i][j], 0.0f);
        }

    for (int c = 0; c < 20; ++c) {
        const int tap = c >> 2;
        const int ch0 = (c & 3) << 6;
        #pragma unroll
        for (int i = 0; i < 4; ++i) {
            int e = tid + i * 256;
            int r = e >> 3, q = e & 7;
            int t = (m0 + r) & (TDEC - 1);
            float4 v = make_float4(0.f, 0.f, 0.f, 0.f);
            if (t + tap - 4 >= 0)
                v = *(const float4*)(XH + (size_t)(m0 + r + tap - 4) * DMODEL + ch0 + q * 8);
            *(float4*)(As + r * CPADH + q * 8) = v;
        }
        #pragma unroll
        for (int i = 0; i < 4; ++i) {
            int e = tid + i * 256;
            int n = e >> 3, q = e & 7;
            int row = (n < 64) ? (n0 + n) : (n0 + 256 + n - 64);
            float4 v = *(const float4*)(Wb + (size_t)row * 1280 + tap * DMODEL + ch0 + q * 8);
            *(float4*)(Bh + n * CPADH + q * 8) = v;
        }
        __syncthreads();
        #pragma unroll
        for (int ks = 0; ks < 4; ++ks) {
            wmma::fragment<wmma::matrix_a, 16, 16, 16, __half, wmma::row_major> af[2];
            wmma::fragment<wmma::matrix_b, 16, 16, 16, __half, wmma::col_major> bfa[2], bfg[2];
            #pragma unroll
            for (int mi = 0; mi < 2; ++mi)
                wmma::load_matrix_sync(af[mi], As + (wm * 32 + mi * 16) * CPADH + ks * 16, CPADH);
            #pragma unroll
            for (int ni = 0; ni < 2; ++ni) {
                wmma::load_matrix_sync(bfa[ni], Bh + (wn * 32 + ni * 16) * CPADH + ks * 16, CPADH);
                wmma::load_matrix_sync(bfg[ni], Bh + (64 + wn * 32 + ni * 16) * CPADH + ks * 16, CPADH);
            }
            #pragma unroll
            for (int mi = 0; mi < 2; ++mi)
                #pragma unroll
                for (int ni = 0; ni < 2; ++ni) {
                    wmma::mma_sync(Ca[mi][ni], af[mi], bfa[ni], Ca[mi][ni]);
                    wmma::mma_sync(Cg[mi][ni], af[mi], bfg[ni], Cg[mi][ni]);
                }
        }
        __syncthreads();
    }

    float* Cb = (float*)smh;
    #pragma unroll
    for (int mi = 0; mi < 2; ++mi)
        #pragma unroll
        for (int ni = 0; ni < 2; ++ni)
            wmma::store_matrix_sync(Cb + (wm * 32 + mi * 16) * EPAD + wn * 32 + ni * 16,
                                    Ca[mi][ni], EPAD, wmma::mem_row_major);
    __syncthreads();
    const int r = tid >> 1;
    const int cc = (tid & 1) * 32;
    float av[32];
    #pragma unroll
    for (int q = 0; q < 8; ++q)
        *(float4*)&av[q * 4] = *(const float4*)(Cb + r * EPAD + cc + q * 4);
    __syncthreads();
    #pragma unroll
    for (int mi = 0; mi < 2; ++mi)
        #pragma unroll
        for (int ni = 0; ni < 2; ++ni)
            wmma::store_matrix_sync(Cb + (wm * 32 + mi * 16) * EPAD + wn * 32 + ni * 16,
                                    Cg[mi][ni], EPAD, wmma::mem_row_major);
    __syncthreads();
    {
        const int m = m0 + r;
        const float* xr = Xres + (size_t)m * DMODEL + n0 + cc;
        float* orow = out + (size_t)m * DMODEL + n0 + cc;
        __half* ohr = outH + (size_t)m * DMODEL + n0 + cc;
        __half* olr = outL + (size_t)m * DMODEL + n0 + cc;
        #pragma unroll
        for (int q = 0; q < 8; ++q) {
            float4 g = *(const float4*)(Cb + r * EPAD + cc + q * 4);
            float4 res = *(const float4*)(xr + q * 4);
            float4 ba = *(const float4*)(bias + n0 + cc + q * 4);
            float4 bg = *(const float4*)(bias + 256 + n0 + cc + q * 4);
            float4 o;
            o.x = fmaf(av[q*4+0] + ba.x, sigf(g.x + bg.x), res.x) * RSQRT2;
            o.y = fmaf(av[q*4+1] + ba.y, sigf(g.y + bg.y), res.y) * RSQRT2;
            o.z = fmaf(av[q*4+2] + ba.z, sigf(g.z + bg.z), res.z) * RSQRT2;
            o.w = fmaf(av[q*4+3] + ba.w, sigf(g.w + bg.w), res.w) * RSQRT2;
            *(float4*)(orow + q * 4) = o;
            __half h[4], l[4];
            split_h(o.x, h[0], l[0]); split_h(o.y, h[1], l[1]);
            split_h(o.z, h[2], l[2]); split_h(o.w, h[3], l[3]);
            *(ulonglong1*)(ohr + q * 4) = *(ulonglong1*)h;
            *(ulonglong1*)(olr + q * 4) = *(ulonglong1*)l;
        }
    }
}

// ================= h3 kernels (R12-proven) =================
#define HPAD 72
#define H3SM ((256 + 128) * HPAD)

// ---------------- scores: S = Q @ enc^T (per batch), N-tile = 128 ----------------
#define SCSM (512 * HPAD)
__global__ void __launch_bounds__(256, 2) k_scores_h3(
    const __half* __restrict__ Qh, const __half* __restrict__ Ql,
    const __half* __restrict__ Eh, const __half* __restrict__ El,
    float* __restrict__ S)
{
    extern __shared__ __align__(16) __half sh[];
    __half* Ah_ = sh;
    __half* Al_ = sh + 128 * HPAD;
    __half* Bh_ = sh + 256 * HPAD;
    __half* Bl_ = sh + 384 * HPAD;
    const int tid = threadIdx.x;
    const int wid = tid >> 5;
    const int b = blockIdx.z;
    const int m0 = blockIdx.x * 128;
    const int n0 = blockIdx.y * 128;
    const int wm = wid & 3;
    const int wn = wid >> 2;
    const __half* Qhb = Qh + ((size_t)b * TDEC + m0) * DMODEL;
    const __half* Qlb = Ql + ((size_t)b * TDEC + m0) * DMODEL;
    const __half* Ehb = Eh + ((size_t)b * TENC + n0) * DMODEL;
    const __half* Elb = El + ((size_t)b * TENC + n0) * DMODEL;
    float* Sb = S + (size_t)b * TDEC * TENC;

    wmma::fragment<wmma::accumulator, 16, 16, 16, float> Cc[2][4];
    #pragma unroll
    for (int i = 0; i < 2; ++i)
        #pragma unroll
        for (int j = 0; j < 4; ++j) wmma::fill_fragment(Cc[i][j], 0.0f);

    for (int c = 0; c < 4; ++c) {
        const int k0 = c * 64;
        #pragma unroll
        for (int i = 0; i < 4; ++i) {
            int e = tid + i * 256;
            int r = e >> 3, q = e & 7;
            *(float4*)(Ah_ + r * HPAD + q * 8) =
                *(const float4*)(Qhb + (size_t)r * DMODEL + k0 + q * 8);
            *(float4*)(Al_ + r * HPAD + q * 8) =
                *(const float4*)(Qlb + (size_t)r * DMODEL + k0 + q * 8);
        }
        #pragma unroll
        for (int i = 0; i < 4; ++i) {
            int e = tid + i * 256;
            int r = e >> 3, q = e & 7;
            *(float4*)(Bh_ + r * HPAD + q * 8) =
                *(const float4*)(Ehb + (size_t)r * DMODEL + k0 + q * 8);
            *(float4*)(Bl_ + r * HPAD + q * 8) =
                *(const float4*)(Elb + (size_t)r * DMODEL + k0 + q * 8);
        }
        __syncthreads();
        #pragma unroll
        for (int ks = 0; ks < 4; ++ks) {
            wmma::fragment<wmma::matrix_a, 16, 16, 16, __half, wmma::row_major> afh[2], afl[2];
            #pragma unroll
            for (int mi = 0; mi < 2; ++mi) {
                wmma::load_matrix_sync(afh[mi], Ah_ + (wm * 32 + mi * 16) * HPAD + ks * 16, HPAD);
                wmma::load_matrix_sync(afl[mi], Al_ + (wm * 32 + mi * 16) * HPAD + ks * 16, HPAD);
            }
            #pragma unroll
            for (int ni = 0; ni < 4; ++ni) {
                wmma::fragment<wmma::matrix_b, 16, 16, 16, __half, wmma::col_major> bfh, bfl;
                wmma::load_matrix_sync(bfh, Bh_ + (wn * 64 + ni * 16) * HPAD + ks * 16, HPAD);
                wmma::load_matrix_sync(bfl, Bl_ + (wn * 64 + ni * 16) * HPAD + ks * 16, HPAD);
                #pragma unroll
                for (int mi = 0; mi < 2; ++mi) {
                    wmma::mma_sync(Cc[mi][ni], afh[mi], bfh, Cc[mi][ni]);
                    wmma::mma_sync(Cc[mi][ni], afh[mi], bfl, Cc[mi][ni]);
                    wmma::mma_sync(Cc[mi][ni], afl[mi], bfh, Cc[mi][ni]);
                }
            }
        }
        __syncthreads();
    }
    #pragma unroll
    for (int mi = 0; mi < 2; ++mi)
        #pragma unroll
        for (int ni = 0; ni < 4; ++ni)
            wmma::store_matrix_sync(
                Sb + (size_t)(m0 + wm * 32 + mi * 16) * TENC + n0 + wn * 64 + ni * 16,
                Cc[mi][ni], TENC, wmma::mem_row_major);
}

// ---------------- softmax: 2 rows/CTA, MLP=2 -> attn hi/lo ----------------
__global__ void __launch_bounds__(256) k_softmax(
    const float* __restrict__ S, __half* __restrict__ Ah, __half* __restrict__ Al)
{
    const int tid = threadIdx.x;
    const int half = tid >> 7;           // 0/1 (warp-aligned)
    const int rt = tid & 127;
    const int wid = tid >> 5;            // 0..7
    const size_t base = ((size_t)blockIdx.x * 2 + half) * TENC;
    __shared__ float red1[8], red2[8];

    float4 v1 = *(const float4*)(S + base + rt * 8);
    float4 v2 = *(const float4*)(S + base + rt * 8 + 4);
    float mx = fmaxf(fmaxf(fmaxf(v1.x, v1.y), fmaxf(v1.z, v1.w)),
                     fmaxf(fmaxf(v2.x, v2.y), fmaxf(v2.z, v2.w)));
    #pragma unroll
    for (int o = 16; o > 0; o >>= 1) mx = fmaxf(mx, __shfl_xor_sync(0xffffffffu, mx, o));
    if ((tid & 31) == 0) red1[wid] = mx;
    __syncthreads();
    {
        int b0 = half * 4;
        mx = fmaxf(fmaxf(red1[b0], red1[b0 + 1]), fmaxf(red1[b0 + 2], red1[b0 + 3]));
    }
    v1.x = __expf(v1.x - mx); v1.y = __expf(v1.y - mx);
    v1.z = __expf(v1.z - mx); v1.w = __expf(v1.w - mx);
    v2.x = __expf(v2.x - mx); v2.y = __expf(v2.y - mx);
    v2.z = __expf(v2.z - mx); v2.w = __expf(v2.w - mx);
    float sm = v1.x + v1.y + v1.z + v1.w + v2.x + v2.y + v2.z + v2.w;
    #pragma unroll
    for (int o = 16; o > 0; o >>= 1) sm += __shfl_xor_sync(0xffffffffu, sm, o);
    if ((tid & 31) == 0) red2[wid] = sm;
    __syncthreads();
    {
        int b0 = half * 4;
        sm = red2[b0] + red2[b0 + 1] + red2[b0 + 2] + red2[b0 + 3];
    }
    float inv = 1.0f / sm;
    v1.x *= inv; v1.y *= inv; v1.z *= inv; v1.w *= inv;
    v2.x *= inv; v2.y *= inv; v2.z *= inv; v2.w *= inv;
    __half h1[4], l1[4], h2[4], l2[4];
    split_h(v1.x, h1[0], l1[0]); split_h(v1.y, h1[1], l1[1]);
    split_h(v1.z, h1[2], l1[2]); split_h(v1.w, h1[3], l1[3]);
    split_h(v2.x, h2[0], l2[0]); split_h(v2.y, h2[1], l2[1]);
    split_h(v2.z, h2[2], l2[2]); split_h(v2.w, h2[3], l2[3]);
    *(ulonglong1*)(Ah + base + rt * 8)     = *(ulonglong1*)h1;
    *(ulonglong1*)(Ah + base + rt * 8 + 4) = *(ulonglong1*)h2;
    *(ulonglong1*)(Al + base + rt * 8)     = *(ulonglong1*)l1;
    *(ulonglong1*)(Al + base + rt * 8 + 4) = *(ulonglong1*)l2;
}

// ---------------- context: H1 = H0 + attn @ V, N-tile = 128 ----------------
#define BPAD 136
#define CXSM (256 * HPAD + 128 * BPAD)
#define EPAD2 132
__global__ void __launch_bounds__(256, 2) k_ctx_h3(
    const __half* __restrict__ AHh, const __half* __restrict__ AHl,
    const __half* __restrict__ Vh, const __half* __restrict__ Vl,
    const float* __restrict__ H0, float* __restrict__ H1, __half* __restrict__ H1H)
{
    extern __shared__ __align__(16) __half sh[];
    __half* Ah_ = sh;
    __half* Al_ = sh + 128 * HPAD;
    __half* Bh_ = sh + 256 * HPAD;
    __half* Bl_ = sh + 256 * HPAD + 64 * BPAD;
    const int tid = threadIdx.x;
    const int wid = tid >> 5;
    const int b = blockIdx.z;
    const int m0 = blockIdx.x * 128;
    const int n0 = blockIdx.y * 128;
    const int wm = wid & 3;
    const int wn = wid >> 2;
    const __half* Ahb = AHh + ((size_t)b * TDEC + m0) * TENC;
    const __half* Alb = AHl + ((size_t)b * TDEC + m0) * TENC;
    const __half* Vhb = Vh + (size_t)b * TENC * DMODEL;
    const __half* Vlb = Vl + (size_t)b * TENC * DMODEL;

    wmma::fragment<wmma::accumulator, 16, 16, 16, float> Cc[2][4];
    #pragma unroll
    for (int i = 0; i < 2; ++i)
        #pragma unroll
        for (int j = 0; j < 4; ++j) wmma::fill_fragment(Cc[i][j], 0.0f);

    for (int c = 0; c < 16; ++c) {
        const int k0 = c * 64;
        #pragma unroll
        for (int i = 0; i < 4; ++i) {
            int e = tid + i * 256;
            int r = e >> 3, q = e & 7;
            *(float4*)(Ah_ + r * HPAD + q * 8) =
                *(const float4*)(Ahb + (size_t)r * TENC + k0 + q * 8);
            *(float4*)(Al_ + r * HPAD + q * 8) =
                *(const float4*)(Alb + (size_t)r * TENC + k0 + q * 8);
        }
        #pragma unroll
        for (int i = 0; i < 4; ++i) {
            int e = tid + i * 256;
            int k = e >> 4, q = e & 15;
            *(float4*)(Bh_ + k * BPAD + q * 8) =
                *(const float4*)(Vhb + (size_t)(k0 + k) * DMODEL + n0 + q * 8);
            *(float4*)(Bl_ + k * BPAD + q * 8) =
                *(const float4*)(Vlb + (size_t)(k0 + k) * DMODEL + n0 + q * 8);
        }
        __syncthreads();
        #pragma unroll
        for (int ks = 0; ks < 4; ++ks) {
            wmma::fragment<wmma::matrix_a, 16, 16, 16, __half, wmma::row_major> afh[2], afl[2];
            #pragma unroll
            for (int mi = 0; mi < 2; ++mi) {
                wmma::load_matrix_sync(afh[mi], Ah_ + (wm * 32 + mi * 16) * HPAD + ks * 16, HPAD);
                wmma::load_matrix_sync(afl[mi], Al_ + (wm * 32 + mi * 16) * HPAD + ks * 16, HPAD);
            }
            #pragma unroll
            for (int ni = 0; ni < 4; ++ni) {
                wmma::fragment<wmma::matrix_b, 16, 16, 16, __half, wmma::row_major> bfh, bfl;
                wmma::load_matrix_sync(bfh, Bh_ + (ks * 16) * BPAD + wn * 64 + ni * 16, BPAD);
                wmma::load_matrix_sync(bfl, Bl_ + (ks * 16) * BPAD + wn * 64 + ni * 16, BPAD);
                #pragma unroll
                for (int mi = 0; mi < 2; ++mi) {
                    wmma::mma_sync(Cc[mi][ni], afh[mi], bfh, Cc[mi][ni]);
                    wmma::mma_sync(Cc[mi][ni], afh[mi], bfl, Cc[mi][ni]);
                    wmma::mma_sync(Cc[mi][ni], afl[mi], bfh, Cc[mi][ni]);
                }
            }
        }
        __syncthreads();
    }

    float* Cb = (float*)sh;
    #pragma unroll
    for (int mi = 0; mi < 2; ++mi)
        #pragma unroll
        for (int ni = 0; ni < 4; ++ni)
            wmma::store_matrix_sync(Cb + (wm * 32 + mi * 16) * EPAD2 + wn * 64 + ni * 16,
                                    Cc[mi][ni], EPAD2, wmma::mem_row_major);
    __syncthreads();
    const int r = tid >> 1;
    const int cc = (tid & 1) * 64;
    const size_t m = (size_t)b * TDEC + m0 + r;
    const float* h0r = H0 + m * DMODEL + n0 + cc;
    float* h1r = H1 + m * DMODEL + n0 + cc;
    __half* hhr = H1H + m * DMODEL + n0 + cc;
    #pragma unroll
    for (int q = 0; q < 16; ++q) {
        float4 cv = *(const float4*)(Cb + r * EPAD2 + cc + q * 4);
        float4 h0 = *(const float4*)(h0r + q * 4);
        float4 o = make_float4(cv.x + h0.x, cv.y + h0.y, cv.z + h0.z, cv.w + h0.w);
        *(float4*)(h1r + q * 4) = o;
        *(__half2*)(hhr + q * 4)     = __floats2half2_rn(o.x, o.y);
        *(__half2*)(hhr + q * 4 + 2) = __floats2half2_rn(o.z, o.w);
    }
}

// ---------------- q-GEMM h3: Q = A @ W^T + b -> Qh/Ql ----------------
__global__ void __launch_bounds__(256, 2) k_qgemm_h3(
    const __half* __restrict__ Ahg, const __half* __restrict__ Alg,
    const __half* __restrict__ Wh, const __half* __restrict__ Wl,
    const float* __restrict__ bias,
    __half* __restrict__ Oh, __half* __restrict__ Ol)
{
    extern __shared__ __align__(16) __half sh[];
    __half* Ah_ = sh;
    __half* Al_ = sh + 128 * HPAD;
    __half* Bh_ = sh + 256 * HPAD;
    __half* Bl_ = sh + 320 * HPAD;
    const int tid = threadIdx.x;
    const int wid = tid >> 5;
    const int m0 = blockIdx.x * 128;
    const int n0 = blockIdx.y * 64;
    const int wm = wid & 3;
    const int wn = wid >> 2;

    wmma::fragment<wmma::accumulator, 16, 16, 16, float> Cc[2][2];
    #pragma unroll
    for (int i = 0; i < 2; ++i)
        #pragma unroll
        for (int j = 0; j < 2; ++j) wmma::fill_fragment(Cc[i][j], 0.0f);

    for (int c = 0; c < 4; ++c) {
        const int k0 = c * 64;
        #pragma unroll
        for (int i = 0; i < 4; ++i) {
            int e = tid + i * 256;
            int r = e >> 3, q = e & 7;
            *(float4*)(Ah_ + r * HPAD + q * 8) =
                *(const float4*)(Ahg + (size_t)(m0 + r) * DMODEL + k0 + q * 8);
            *(float4*)(Al_ + r * HPAD + q * 8) =
                *(const float4*)(Alg + (size_t)(m0 + r) * DMODEL + k0 + q * 8);
        }
        #pragma unroll
        for (int i = 0; i < 2; ++i) {
            int e = tid + i * 256;
            int n = e >> 3, q = e & 7;
            *(float4*)(Bh_ + n * HPAD + q * 8) =
                *(const float4*)(Wh + (size_t)(n0 + n) * DMODEL + k0 + q * 8);
            *(float4*)(Bl_ + n * HPAD + q * 8) =
                *(const float4*)(Wl + (size_t)(n0 + n) * DMODEL + k0 + q * 8);
        }
        __syncthreads();
        #pragma unroll
        for (int ks = 0; ks < 4; ++ks) {
            wmma::fragment<wmma::matrix_a, 16, 16, 16, __half, wmma::row_major> afh[2], afl[2];
            wmma::fragment<wmma::matrix_b, 16, 16, 16, __half, wmma::col_major> bfh[2], bfl[2];
            #pragma unroll
            for (int mi = 0; mi < 2; ++mi) {
                wmma::load_matrix_sync(afh[mi], Ah_ + (wm * 32 + mi * 16) * HPAD + ks * 16, HPAD);
                wmma::load_matrix_sync(afl[mi], Al_ + (wm * 32 + mi * 16) * HPAD + ks * 16, HPAD);
            }
            #pragma unroll
            for (int ni = 0; ni < 2; ++ni) {
                wmma::load_matrix_sync(bfh[ni], Bh_ + (wn * 32 + ni * 16) * HPAD + ks * 16, HPAD);
                wmma::load_matrix_sync(bfl[ni], Bl_ + (wn * 32 + ni * 16) * HPAD + ks * 16, HPAD);
            }
            #pragma unroll
            for (int mi = 0; mi < 2; ++mi)
                #pragma unroll
                for (int ni = 0; ni < 2; ++ni) {
                    wmma::mma_sync(Cc[mi][ni], afh[mi], bfh[ni], Cc[mi][ni]);
                    wmma::mma_sync(Cc[mi][ni], afh[mi], bfl[ni], Cc[mi][ni]);
                    wmma::mma_sync(Cc[mi][ni], afl[mi], bfh[ni], Cc[mi][ni]);
                }
        }
        __syncthreads();
    }

    float* Cb = (float*)sh;
    #pragma unroll
    for (int mi = 0; mi < 2; ++mi)
        #pragma unroll
        for (int ni = 0; ni < 2; ++ni)
            wmma::store_matrix_sync(Cb + (wm * 32 + mi * 16) * EPAD + wn * 32 + ni * 16,
                                    Cc[mi][ni], EPAD, wmma::mem_row_major);
    __syncthreads();
    const int r = tid >> 1;
    const int cc = (tid & 1) * 32;
    const int m = m0 + r;
    __half* ohr = Oh + (size_t)m * DMODEL + n0 + cc;
    __half* olr = Ol + (size_t)m * DMODEL + n0 + cc;
    #pragma unroll
    for (int q = 0; q < 8; ++q) {
        float4 cv = *(const float4*)(Cb + r * EPAD + cc + q * 4);
        float4 bb = *(const float4*)(bias + n0 + cc + q * 4);
        __half h[4], l[4];
        split_h(cv.x + bb.x, h[0], l[0]); split_h(cv.y + bb.y, h[1], l[1]);
        split_h(cv.z + bb.z, h[2], l[2]); split_h(cv.w + bb.w, h[3], l[3]);
        *(ulonglong1*)(ohr + q * 4) = *(ulonglong1*)h;
        *(ulonglong1*)(olr + q * 4) = *(ulonglong1*)l;
    }
}

// ---------------- proj h3 (N=80 predicated) ----------------
__global__ void __launch_bounds__(256, 2) k_proj_h3(
    const __half* __restrict__ Ahg, const __half* __restrict__ Alg,
    const __half* __restrict__ Wh, const __half* __restrict__ Wl,
    const float* __restrict__ bias, float* __restrict__ out)
{
    extern __shared__ __align__(16) __half sh[];
    __half* Ah_ = sh;
    __half* Al_ = sh + 128 * HPAD;
    __half* Bh_ = sh + 256 * HPAD;
    __half* Bl_ = sh + 320 * HPAD;
    const int tid = threadIdx.x;
    const int wid = tid >> 5;
    const int m0 = blockIdx.x * 128;
    const int n0 = blockIdx.y * 64;
    const int wm = wid & 3;
    const int wn = wid >> 2;

    wmma::fragment<wmma::accumulator, 16, 16, 16, float> Cc[2][2];
    #pragma unroll
    for (int i = 0; i < 2; ++i)
        #pragma unroll
        for (int j = 0; j < 2; ++j) wmma::fill_fragment(Cc[i][j], 0.0f);

    for (int c = 0; c < 4; ++c) {
        const int k0 = c * 64;
        #pragma unroll
        for (int i = 0; i < 4; ++i) {
            int e = tid + i * 256;
            int r = e >> 3, q = e & 7;
            *(float4*)(Ah_ + r * HPAD + q * 8) =
                *(const float4*)(Ahg + (size_t)(m0 + r) * DMODEL + k0 + q * 8);
            *(float4*)(Al_ + r * HPAD + q * 8) =
                *(const float4*)(Alg + (size_t)(m0 + r) * DMODEL + k0 + q * 8);
        }
        #pragma unroll
        for (int i = 0; i < 2; ++i) {
            int e = tid + i * 256;
            int n = e >> 3, q = e & 7;
            int row = n0 + n;
            float4 vh = make_float4(0.f, 0.f, 0.f, 0.f);
            float4 vl = vh;
            if (row < INDIM) {
                vh = *(const float4*)(Wh + (size_t)row * DMODEL + k0 + q * 8);
                vl = *(const float4*)(Wl + (size_t)row * DMODEL + k0 + q * 8);
            }
            *(float4*)(Bh_ + n * HPAD + q * 8) = vh;
            *(float4*)(Bl_ + n * HPAD + q * 8) = vl;
        }
        __syncthreads();
        #pragma unroll
        for (int ks = 0; ks < 4; ++ks) {
            wmma::fragment<wmma::matrix_a, 16, 16, 16, __half, wmma::row_major> afh[2], afl[2];
            wmma::fragment<wmma::matrix_b, 16, 16, 16, __half, wmma::col_major> bfh[2], bfl[2];
            #pragma unroll
            for (int mi = 0; mi < 2; ++mi) {
                wmma::load_matrix_sync(afh[mi], Ah_ + (wm * 32 + mi * 16) * HPAD + ks * 16, HPAD);
                wmma::load_matrix_sync(afl[mi], Al_ + (wm * 32 + mi * 16) * HPAD + ks * 16, HPAD);
            }
            #pragma unroll
            for (int ni = 0; ni < 2; ++ni) {
                wmma::load_matrix_sync(bfh[ni], Bh_ + (wn * 32 + ni * 16) * HPAD + ks * 16, HPAD);
                wmma::load_matrix_sync(bfl[ni], Bl_ + (wn * 32 + ni * 16) * HPAD + ks * 16, HPAD);
            }
            #pragma unroll
            for (int mi = 0; mi < 2; ++mi)
                #pragma unroll
                for (int ni = 0; ni < 2; ++ni) {
                    wmma::mma_sync(Cc[mi][ni], afh[mi], bfh[ni], Cc[mi][ni]);
                    wmma::mma_sync(Cc[mi][ni], afh[mi], bfl[ni], Cc[mi][ni]);
                    wmma::mma_sync(Cc[mi][ni], afl[mi], bfh[ni], Cc[mi][ni]);
                }
        }
        __syncthreads();
    }

    float* Cb = (float*)sh;
    #pragma unroll
    for (int mi = 0; mi < 2; ++mi)
        #pragma unroll
        for (int ni = 0; ni < 2; ++ni)
            wmma::store_matrix_sync(Cb + (wm * 32 + mi * 16) * EPAD + wn * 32 + ni * 16,
                                    Cc[mi][ni], EPAD, wmma::mem_row_major);
    __syncthreads();
    const int r = tid >> 1;
    const int cc = (tid & 1) * 32;
    const int m = m0 + r;
    #pragma unroll
    for (int q = 0; q < 8; ++q) {
        int col = n0 + cc + q * 4;
        if (col < INDIM) {
            float4 cv = *(const float4*)(Cb + r * EPAD + cc + q * 4);
            float4 bb = *(const float4*)(bias + col);
            *(float4*)(out + (size_t)m * INDIM + col) =
                make_float4(cv.x + bb.x, cv.y + bb.y, cv.z + bb.z, cv.w + bb.w);
        }
    }
}

// ---------------- lin_shift h3: x = shift_right(mel @ W_lin^T + b); X fp32 + XH hi ----------------
#define LPAD 88
#define LNSM (384 * LPAD)   // halves: Ah,Al 128 rows + Bh,Bl 64 rows
__global__ void __launch_bounds__(256, 2) k_lin_h3(
    const float* __restrict__ mel, const float* __restrict__ W,
    const float* __restrict__ bias, float* __restrict__ out,
    __half* __restrict__ outH)
{
    extern __shared__ __align__(16) __half sh[];
    __half* Ah_ = sh;
    __half* Al_ = sh + 128 * LPAD;
    __half* Bh_ = sh + 256 * LPAD;
    __half* Bl_ = sh + 320 * LPAD;
    const int tid = threadIdx.x;
    const int wid = tid >> 5;
    const int m0 = blockIdx.x * 128;
    const int n0 = blockIdx.y * 64;
    const int wm = wid & 3;
    const int wn = wid >> 2;

    // fill A: 128 rows x 80 fp32 -> hi/lo (shifted, t==0 row zero). 2560 float4s.
    #pragma unroll
    for (int i = 0; i < 10; ++i) {
        int e = tid + i * 256;
        int r = e / 20, p = e % 20;
        int m = m0 + r;
        int t = m & (TDEC - 1);
        float4 v = make_float4(0.f, 0.f, 0.f, 0.f);
        if (t > 0) v = *(const float4*)(mel + (size_t)(m - 1) * INDIM + p * 4);
        __half h[4], l[4];
        split_h(v.x, h[0], l[0]); split_h(v.y, h[1], l[1]);
        split_h(v.z, h[2], l[2]); split_h(v.w, h[3], l[3]);
        *(ulonglong1*)(Ah_ + r * LPAD + p * 4) = *(ulonglong1*)h;
        *(ulonglong1*)(Al_ + r * LPAD + p * 4) = *(ulonglong1*)l;
    }
    // fill B: 64 rows x 80 fp32 -> hi/lo. 1280 float4s.
    #pragma unroll
    for (int i = 0; i < 5; ++i) {
        int e = tid + i * 256;
        int n = e / 20, p = e % 20;
        float4 v = *(const float4*)(W + (size_t)(n0 + n) * INDIM + p * 4);
        __half h[4], l[4];
        split_h(v.x, h[0], l[0]); split_h(v.y, h[1], l[1]);
        split_h(v.z, h[2], l[2]); split_h(v.w, h[3], l[3]);
        *(ulonglong1*)(Bh_ + n * LPAD + p * 4) = *(ulonglong1*)h;
        *(ulonglong1*)(Bl_ + n * LPAD + p * 4) = *(ulonglong1*)l;
    }
    __syncthreads();

    wmma::fragment<wmma::accumulator, 16, 16, 16, float> Cc[2][2];
    #pragma unroll
    for (int i = 0; i < 2; ++i)
        #pragma unroll
        for (int j = 0; j < 2; ++j) wmma::fill_fragment(Cc[i][j], 0.0f);

    #pragma unroll
    for (int ks = 0; ks < 5; ++ks) {
        wmma::fragment<wmma::matrix_a, 16, 16, 16, __half, wmma::row_major> afh[2], afl[2];
        wmma::fragment<wmma::matrix_b, 16, 16, 16, __half, wmma::col_major> bfh[2], bfl[2];
        #pragma unroll
        for (int mi = 0; mi < 2; ++mi) {
            wmma::load_matrix_sync(afh[mi], Ah_ + (wm * 32 + mi * 16) * LPAD + ks * 16, LPAD);
            wmma::load_matrix_sync(afl[mi], Al_ + (wm * 32 + mi * 16) * LPAD + ks * 16, LPAD);
        }
        #pragma unroll
        for (int ni = 0; ni < 2; ++ni) {
            wmma::load_matrix_sync(bfh[ni], Bh_ + (wn * 32 + ni * 16) * LPAD + ks * 16, LPAD);
            wmma::load_matrix_sync(bfl[ni], Bl_ + (wn * 32 + ni * 16) * LPAD + ks * 16, LPAD);
        }
        #pragma unroll
        for (int mi = 0; mi < 2; ++mi)
            #pragma unroll
            for (int ni = 0; ni < 2; ++ni) {
                wmma::mma_sync(Cc[mi][ni], afh[mi], bfh[ni], Cc[mi][ni]);
                wmma::mma_sync(Cc[mi][ni], afh[mi], bfl[ni], Cc[mi][ni]);
                wmma::mma_sync(Cc[mi][ni], afl[mi], bfh[ni], Cc[mi][ni]);
            }
    }
    __syncthreads();

    float* Cb = (float*)sh;
    #pragma unroll
    for (int mi = 0; mi < 2; ++mi)
        #pragma unroll
        for (int ni = 0; ni < 2; ++ni)
            wmma::store_matrix_sync(Cb + (wm * 32 + mi * 16) * EPAD + wn * 32 + ni * 16,
                                    Cc[mi][ni], EPAD, wmma::mem_row_major);
    __syncthreads();
    const int r = tid >> 1;
    const int cc = (tid & 1) * 32;
    const int m = m0 + r;
    const int t = m & (TDEC - 1);
    float* orow = out + (size_t)m * DMODEL + n0 + cc;
    __half* ohr = outH + (size_t)m * DMODEL + n0 + cc;
    #pragma unroll
    for (int q = 0; q < 8; ++q) {
        float4 o = make_float4(0.f, 0.f, 0.f, 0.f);
        if (t > 0) {
            float4 cv = *(const float4*)(Cb + r * EPAD + cc + q * 4);
            float4 bb = *(const float4*)(bias + n0 + cc + q * 4);
            o = make_float4(cv.x + bb.x, cv.y + bb.y, cv.z + bb.z, cv.w + bb.w);
        }
        *(float4*)(orow + q * 4) = o;
        *(__half2*)(ohr + q * 4)     = __floats2half2_rn(o.x, o.y);
        *(__half2*)(ohr + q * 4 + 2) = __floats2half2_rn(o.z, o.w);
    }
}

// ---------------- launch ----------------
extern "C" void kernel_launch(void* const* d_in, const int* in_sizes, int n_in,
                              void* d_out, int out_size)
{
    (void)in_sizes; (void)n_in; (void)out_size;
    const float* enc   = (const float*)d_in[0];
    const float* first = (const float*)d_in[1];
    const float* mel   = (const float*)d_in[2];
    const float* W_lin = (const float*)d_in[3];
    const float* b_lin = (const float*)d_in[4];
    const float* cw0   = (const float*)d_in[5];
    const float* cb0   = (const float*)d_in[6];
    const float* cw1   = (const float*)d_in[7];
    const float* cb1   = (const float*)d_in[8];
    const float* W_att = (const float*)d_in[9];
    const float* b_att = (const float*)d_in[10];
    const float* W_prj = (const float*)d_in[11];
    const float* b_prj = (const float*)d_in[12];
    float* out = (float*)d_out;

    float *X, *H0, *H1, *S;
    __half *XH, *H0h, *H0l, *Qh, *Ql, *AHh, *AHl, *EHh, *EHl, *VHh, *VHl;
    __half *WbH0, *WbH1, *WAh, *WAl, *WPh, *WPl;
    cudaGetSymbolAddress((void**)&X,  g_X);
    cudaGetSymbolAddress((void**)&H0, g_H0);
    cudaGetSymbolAddress((void**)&H1, g_H1);
    cudaGetSymbolAddress((void**)&S,  g_S);
    cudaGetSymbolAddress((void**)&XH, g_XH);
    cudaGetSymbolAddress((void**)&H0h, g_H0h);
    cudaGetSymbolAddress((void**)&H0l, g_H0l);
    cudaGetSymbolAddress((void**)&Qh, g_Qh);
    cudaGetSymbolAddress((void**)&Ql, g_Ql);
    cudaGetSymbolAddress((void**)&AHh, g_AHh);
    cudaGetSymbolAddress((void**)&AHl, g_AHl);
    cudaGetSymbolAddress((void**)&EHh, g_EHh);
    cudaGetSymbolAddress((void**)&EHl, g_EHl);
    cudaGetSymbolAddress((void**)&VHh, g_VHh);
    cudaGetSymbolAddress((void**)&VHl, g_VHl);
    cudaGetSymbolAddress((void**)&WbH0, g_WbH0);
    cudaGetSymbolAddress((void**)&WbH1, g_WbH1);
    cudaGetSymbolAddress((void**)&WAh, g_WAh);
    cudaGetSymbolAddress((void**)&WAl, g_WAl);
    cudaGetSymbolAddress((void**)&WPh, g_WPh);
    cudaGetSymbolAddress((void**)&WPl, g_WPl);

    const int CONV_SMEM = SMH * 2;    // 36864 B
    const int H3_SMEM   = H3SM * 2;   // 55296 B
    const int SC_SMEM   = SCSM * 2;   // 73728 B
    const int CX_SMEM   = CXSM * 2;   // 71680 B
    const int LN_SMEM   = LNSM * 2;   // 67584 B
    cudaFuncSetAttribute(k_conv_wmma, cudaFuncAttributeMaxDynamicSharedMemorySize, CONV_SMEM);
    cudaFuncSetAttribute(k_scores_h3, cudaFuncAttributeMaxDynamicSharedMemorySize, SC_SMEM);
    cudaFuncSetAttribute(k_ctx_h3,    cudaFuncAttributeMaxDynamicSharedMemorySize, CX_SMEM);
    cudaFuncSetAttribute(k_qgemm_h3,  cudaFuncAttributeMaxDynamicSharedMemorySize, H3_SMEM);
    cudaFuncSetAttribute(k_proj_h3,   cudaFuncAttributeMaxDynamicSharedMemorySize, H3_SMEM);
    cudaFuncSetAttribute(k_lin_h3,    cudaFuncAttributeMaxDynamicSharedMemorySize, LN_SMEM);

    k_repack_nk<<<(C2 * DMODEL * 5 + 255) / 256, 256>>>(cw0, WbH0);
    k_repack_nk<<<(C2 * DMODEL * 5 + 255) / 256, 256>>>(cw1, WbH1);
    k_prep_enc<<<(BDIM * TENC * DMODEL / 4) / 256, 256>>>(enc, first, EHh, EHl, VHh, VHl);
    k_split<<<(DMODEL * DMODEL / 4) / 256, 256>>>(W_att, WAh, WAl);
    k_split<<<(INDIM * DMODEL / 4) / 256, 256>>>(W_prj, WPh, WPl);
    k_lin_h3<<<dim3(MTOT / 128, DMODEL / 64), 256, LN_SMEM>>>(mel, W_lin, b_lin, X, XH);
    k_conv_wmma<<<dim3(MTOT / 128, DMODEL / 64), 256, CONV_SMEM>>>(
        X, XH, WbH0, cb0, H0, H0h, H0l);
    k_qgemm_h3<<<dim3(MTOT / 128, DMODEL / 64), 256, H3_SMEM>>>(
        H0h, H0l, WAh, WAl, b_att, Qh, Ql);
    k_scores_h3<<<dim3(TDEC / 128, TENC / 128, BDIM), 256, SC_SMEM>>>(Qh, Ql, EHh, EHl, S);
    k_softmax<<<MTOT / 2, 256>>>(S, AHh, AHl);
    k_ctx_h3<<<dim3(TDEC / 128, DMODEL / 128, BDIM), 256, CX_SMEM>>>(
        AHh, AHl, VHh, VHl, H0, H1, XH);
    k_conv_wmma<<<dim3(MTOT / 128, DMODEL / 64), 256, CONV_SMEM>>>(
        H1, XH, WbH1, cb1, X, H0h, H0l);
    k_proj_h3<<<dim3(MTOT / 128, 2), 256, H3_SMEM>>>(H0h, H0l, WPh, WPl, b_prj, out);
}

// round 15
// speedup vs baseline: 1.0178x; 1.0178x over previous
#include <cuda_runtime.h>
#include <cuda_fp16.h>
#include <math.h>
#include <stdint.h>
#include <mma.h>

using namespace nvcuda;

#define BDIM   32
#define TENC   1024
#define TDEC   2048
#define DMODEL 256
#define INDIM  80
#define C2     512
#define MTOT   (BDIM*TDEC)
#define RSQRT2 0.70710678118654752440f

typedef unsigned long long u64;

// ---------------- scratch ----------------
__device__ float  g_X [(size_t)MTOT*DMODEL];
__device__ float  g_H0[(size_t)MTOT*DMODEL];
__device__ float  g_H1[(size_t)MTOT*DMODEL];
__device__ __half g_XH[(size_t)MTOT*DMODEL];
__device__ __half g_H0h[(size_t)MTOT*DMODEL];
__device__ __half g_H0l[(size_t)MTOT*DMODEL];
__device__ __half g_Qh[(size_t)MTOT*DMODEL];
__device__ __half g_Ql[(size_t)MTOT*DMODEL];
__device__ float  g_S [(size_t)BDIM*TDEC*TENC];
__device__ __half g_AHh[(size_t)BDIM*TDEC*TENC];
__device__ __half g_AHl[(size_t)BDIM*TDEC*TENC];
__device__ __half g_EHh[(size_t)BDIM*TENC*DMODEL];
__device__ __half g_EHl[(size_t)BDIM*TENC*DMODEL];
__device__ __half g_VHh[(size_t)BDIM*TENC*DMODEL];
__device__ __half g_VHl[(size_t)BDIM*TENC*DMODEL];
__device__ __half g_WbH0[(size_t)C2*1280];
__device__ __half g_WbH1[(size_t)C2*1280];
__device__ __half g_WAh[(size_t)DMODEL*DMODEL];
__device__ __half g_WAl[(size_t)DMODEL*DMODEL];
__device__ __half g_WPh[(size_t)INDIM*DMODEL];
__device__ __half g_WPl[(size_t)INDIM*DMODEL];

__device__ __forceinline__ float sigf(float x) { return 1.0f / (1.0f + __expf(-x)); }
__device__ __forceinline__ void split_h(float x, __half &hi, __half &lo) {
    hi = __float2half_rn(x);
    lo = __float2half_rn(x - __half2float(hi));
}

// ------- packed f32x2 helpers (lin_shift only) -------
__device__ __forceinline__ u64 pack_dup(float x) {
    u64 r; asm("mov.b64 %0, {%1, %1};" : "=l"(r) : "f"(x)); return r;
}
__device__ __forceinline__ void ffma2(u64 &d, u64 a, u64 b) {
    asm("fma.rn.f32x2 %0, %1, %2, %0;" : "+l"(d) : "l"(a), "l"(b));
}
__device__ __forceinline__ float2 unpk(u64 v) {
    float lo, hi; asm("mov.b64 {%0, %1}, %2;" : "=f"(lo), "=f"(hi) : "l"(v));
    return make_float2(lo, hi);
}

// ---------------- weight repack + fp16 round ----------------
__global__ void __launch_bounds__(256) k_repack_nk(const float* __restrict__ w,
                                                   __half* __restrict__ wb)
{
    int i = blockIdx.x * 256 + threadIdx.x;
    if (i >= C2 * DMODEL * 5) return;
    int n   = i / (DMODEL * 5);
    int rem = i - n * (DMODEL * 5);
    int ch  = rem / 5;
    int tap = rem - ch * 5;
    wb[(size_t)n * 1280 + tap * DMODEL + ch] = __float2half_rn(w[i]);
}

// ---------------- enc/V prep ----------------
__global__ void __launch_bounds__(256) k_prep_enc(
    const float* __restrict__ enc, const float* __restrict__ first,
    __half* __restrict__ Eh, __half* __restrict__ El,
    __half* __restrict__ Vh, __half* __restrict__ Vl)
{
    size_t i = (size_t)blockIdx.x * 256 + threadIdx.x;
    float4 e = *(const float4*)(enc + i * 4);
    float4 f = *(const float4*)(first + i * 4);
    __half eh[4], el[4], vh[4], vl[4];
    split_h(e.x, eh[0], el[0]); split_h(e.y, eh[1], el[1]);
    split_h(e.z, eh[2], el[2]); split_h(e.w, eh[3], el[3]);
    split_h(e.x + f.x, vh[0], vl[0]); split_h(e.y + f.y, vh[1], vl[1]);
    split_h(e.z + f.z, vh[2], vl[2]); split_h(e.w + f.w, vh[3], vl[3]);
    *(ulonglong1*)(Eh + i * 4) = *(ulonglong1*)eh;
    *(ulonglong1*)(El + i * 4) = *(ulonglong1*)el;
    *(ulonglong1*)(Vh + i * 4) = *(ulonglong1*)vh;
    *(ulonglong1*)(Vl + i * 4) = *(ulonglong1*)vl;
}

// ---------------- fp32 -> hi/lo split (weights only) ----------------
__global__ void __launch_bounds__(256) k_split(
    const float* __restrict__ x, __half* __restrict__ hi, __half* __restrict__ lo)
{
    size_t i = (size_t)blockIdx.x * 256 + threadIdx.x;
    float4 v = *(const float4*)(x + i * 4);
    __half h[4], l[4];
    split_h(v.x, h[0], l[0]); split_h(v.y, h[1], l[1]);
    split_h(v.z, h[2], l[2]); split_h(v.w, h[3], l[3]);
    *(ulonglong1*)(hi + i * 4) = *(ulonglong1*)h;
    *(ulonglong1*)(lo + i * 4) = *(ulonglong1*)l;
}

// ================= conv: fp16 wmma single-buffer + hi/lo epilogue (R12-proven) =================
#define CPADH 72
#define SMH   (256*CPADH)
#define EPAD  68
__global__ void __launch_bounds__(256, 2) k_conv_wmma(
    const float* __restrict__ Xres, const __half* __restrict__ XH,
    const __half* __restrict__ Wb, const float* __restrict__ bias,
    float* __restrict__ out, __half* __restrict__ outH, __half* __restrict__ outL,
    int writeF32)
{
    extern __shared__ __align__(16) __half smh[];
    __half* As = smh;
    __half* Bh = smh + 128 * CPADH;
    const int tid = threadIdx.x;
    const int wid = tid >> 5;
    const int m0 = blockIdx.x * 128;
    const int n0 = blockIdx.y * 64;
    const int wm = wid & 3;
    const int wn = wid >> 2;

    wmma::fragment<wmma::accumulator, 16, 16, 16, float> Ca[2][2], Cg[2][2];
    #pragma unroll
    for (int i = 0; i < 2; ++i)
        #pragma unroll
        for (int j = 0; j < 2; ++j) {
            wmma::fill_fragment(Ca[i][j], 0.0f);
            wmma::fill_fragment(Cg[i][j], 0.0f);
        }

    for (int c = 0; c < 20; ++c) {
        const int tap = c >> 2;
        const int ch0 = (c & 3) << 6;
        #pragma unroll
        for (int i = 0; i < 4; ++i) {
            int e = tid + i * 256;
            int r = e >> 3, q = e & 7;
            int t = (m0 + r) & (TDEC - 1);
            float4 v = make_float4(0.f, 0.f, 0.f, 0.f);
            if (t + tap - 4 >= 0)
                v = *(const float4*)(XH + (size_t)(m0 + r + tap - 4) * DMODEL + ch0 + q * 8);
            *(float4*)(As + r * CPADH + q * 8) = v;
        }
        #pragma unroll
        for (int i = 0; i < 4; ++i) {
            int e = tid + i * 256;
            int n = e >> 3, q = e & 7;
            int row = (n < 64) ? (n0 + n) : (n0 + 256 + n - 64);
            float4 v = *(const float4*)(Wb + (size_t)row * 1280 + tap * DMODEL + ch0 + q * 8);
            *(float4*)(Bh + n * CPADH + q * 8) = v;
        }
        __syncthreads();
        #pragma unroll
        for (int ks = 0; ks < 4; ++ks) {
            wmma::fragment<wmma::matrix_a, 16, 16, 16, __half, wmma::row_major> af[2];
            wmma::fragment<wmma::matrix_b, 16, 16, 16, __half, wmma::col_major> bfa[2], bfg[2];
            #pragma unroll
            for (int mi = 0; mi < 2; ++mi)
                wmma::load_matrix_sync(af[mi], As + (wm * 32 + mi * 16) * CPADH + ks * 16, CPADH);
            #pragma unroll
            for (int ni = 0; ni < 2; ++ni) {
                wmma::load_matrix_sync(bfa[ni], Bh + (wn * 32 + ni * 16) * CPADH + ks * 16, CPADH);
                wmma::load_matrix_sync(bfg[ni], Bh + (64 + wn * 32 + ni * 16) * CPADH + ks * 16, CPADH);
            }
            #pragma unroll
            for (int mi = 0; mi < 2; ++mi)
                #pragma unroll
                for (int ni = 0; ni < 2; ++ni) {
                    wmma::mma_sync(Ca[mi][ni], af[mi], bfa[ni], Ca[mi][ni]);
                    wmma::mma_sync(Cg[mi][ni], af[mi], bfg[ni], Cg[mi][ni]);
                }
        }
        __syncthreads();
    }

    float* Cb = (float*)smh;
    #pragma unroll
    for (int mi = 0; mi < 2; ++mi)
        #pragma unroll
        for (int ni = 0; ni < 2; ++ni)
            wmma::store_matrix_sync(Cb + (wm * 32 + mi * 16) * EPAD + wn * 32 + ni * 16,
                                    Ca[mi][ni], EPAD, wmma::mem_row_major);
    __syncthreads();
    const int r = tid >> 1;
    const int cc = (tid & 1) * 32;
    float av[32];
    #pragma unroll
    for (int q = 0; q < 8; ++q)
        *(float4*)&av[q * 4] = *(const float4*)(Cb + r * EPAD + cc + q * 4);
    __syncthreads();
    #pragma unroll
    for (int mi = 0; mi < 2; ++mi)
        #pragma unroll
        for (int ni = 0; ni < 2; ++ni)
            wmma::store_matrix_sync(Cb + (wm * 32 + mi * 16) * EPAD + wn * 32 + ni * 16,
                                    Cg[mi][ni], EPAD, wmma::mem_row_major);
    __syncthreads();
    {
        const int m = m0 + r;
        const float* xr = Xres + (size_t)m * DMODEL + n0 + cc;
        float* orow = out + (size_t)m * DMODEL + n0 + cc;
        __half* ohr = outH + (size_t)m * DMODEL + n0 + cc;
        __half* olr = outL + (size_t)m * DMODEL + n0 + cc;
        #pragma unroll
        for (int q = 0; q < 8; ++q) {
            float4 g = *(const float4*)(Cb + r * EPAD + cc + q * 4);
            float4 res = *(const float4*)(xr + q * 4);
            float4 ba = *(const float4*)(bias + n0 + cc + q * 4);
            float4 bg = *(const float4*)(bias + 256 + n0 + cc + q * 4);
            float4 o;
            o.x = fmaf(av[q*4+0] + ba.x, sigf(g.x + bg.x), res.x) * RSQRT2;
            o.y = fmaf(av[q*4+1] + ba.y, sigf(g.y + bg.y), res.y) * RSQRT2;
            o.z = fmaf(av[q*4+2] + ba.z, sigf(g.z + bg.z), res.z) * RSQRT2;
            o.w = fmaf(av[q*4+3] + ba.w, sigf(g.w + bg.w), res.w) * RSQRT2;
            if (writeF32) *(float4*)(orow + q * 4) = o;
            __half h[4], l[4];
            split_h(o.x, h[0], l[0]); split_h(o.y, h[1], l[1]);
            split_h(o.z, h[2], l[2]); split_h(o.w, h[3], l[3]);
            *(ulonglong1*)(ohr + q * 4) = *(ulonglong1*)h;
            *(ulonglong1*)(olr + q * 4) = *(ulonglong1*)l;
        }
    }
}

// ================= h3 kernels (R12-proven) =================
#define HPAD 72
#define H3SM ((256 + 128) * HPAD)

// ---------------- scores: S = Q @ enc^T (per batch), N-tile = 128 ----------------
#define SCSM (512 * HPAD)
__global__ void __launch_bounds__(256, 2) k_scores_h3(
    const __half* __restrict__ Qh, const __half* __restrict__ Ql,
    const __half* __restrict__ Eh, const __half* __restrict__ El,
    float* __restrict__ S)
{
    extern __shared__ __align__(16) __half sh[];
    __half* Ah_ = sh;
    __half* Al_ = sh + 128 * HPAD;
    __half* Bh_ = sh + 256 * HPAD;
    __half* Bl_ = sh + 384 * HPAD;
    const int tid = threadIdx.x;
    const int wid = tid >> 5;
    const int b = blockIdx.z;
    const int m0 = blockIdx.x * 128;
    const int n0 = blockIdx.y * 128;
    const int wm = wid & 3;
    const int wn = wid >> 2;
    const __half* Qhb = Qh + ((size_t)b * TDEC + m0) * DMODEL;
    const __half* Qlb = Ql + ((size_t)b * TDEC + m0) * DMODEL;
    const __half* Ehb = Eh + ((size_t)b * TENC + n0) * DMODEL;
    const __half* Elb = El + ((size_t)b * TENC + n0) * DMODEL;
    float* Sb = S + (size_t)b * TDEC * TENC;

    wmma::fragment<wmma::accumulator, 16, 16, 16, float> Cc[2][4];
    #pragma unroll
    for (int i = 0; i < 2; ++i)
        #pragma unroll
        for (int j = 0; j < 4; ++j) wmma::fill_fragment(Cc[i][j], 0.0f);

    for (int c = 0; c < 4; ++c) {
        const int k0 = c * 64;
        #pragma unroll
        for (int i = 0; i < 4; ++i) {
            int e = tid + i * 256;
            int r = e >> 3, q = e & 7;
            *(float4*)(Ah_ + r * HPAD + q * 8) =
                *(const float4*)(Qhb + (size_t)r * DMODEL + k0 + q * 8);
            *(float4*)(Al_ + r * HPAD + q * 8) =
                *(const float4*)(Qlb + (size_t)r * DMODEL + k0 + q * 8);
        }
        #pragma unroll
        for (int i = 0; i < 4; ++i) {
            int e = tid + i * 256;
            int r = e >> 3, q = e & 7;
            *(float4*)(Bh_ + r * HPAD + q * 8) =
                *(const float4*)(Ehb + (size_t)r * DMODEL + k0 + q * 8);
            *(float4*)(Bl_ + r * HPAD + q * 8) =
                *(const float4*)(Elb + (size_t)r * DMODEL + k0 + q * 8);
        }
        __syncthreads();
        #pragma unroll
        for (int ks = 0; ks < 4; ++ks) {
            wmma::fragment<wmma::matrix_a, 16, 16, 16, __half, wmma::row_major> afh[2], afl[2];
            #pragma unroll
            for (int mi = 0; mi < 2; ++mi) {
                wmma::load_matrix_sync(afh[mi], Ah_ + (wm * 32 + mi * 16) * HPAD + ks * 16, HPAD);
                wmma::load_matrix_sync(afl[mi], Al_ + (wm * 32 + mi * 16) * HPAD + ks * 16, HPAD);
            }
            #pragma unroll
            for (int ni = 0; ni < 4; ++ni) {
                wmma::fragment<wmma::matrix_b, 16, 16, 16, __half, wmma::col_major> bfh, bfl;
                wmma::load_matrix_sync(bfh, Bh_ + (wn * 64 + ni * 16) * HPAD + ks * 16, HPAD);
                wmma::load_matrix_sync(bfl, Bl_ + (wn * 64 + ni * 16) * HPAD + ks * 16, HPAD);
                #pragma unroll
                for (int mi = 0; mi < 2; ++mi) {
                    wmma::mma_sync(Cc[mi][ni], afh[mi], bfh, Cc[mi][ni]);
                    wmma::mma_sync(Cc[mi][ni], afh[mi], bfl, Cc[mi][ni]);
                    wmma::mma_sync(Cc[mi][ni], afl[mi], bfh, Cc[mi][ni]);
                }
            }
        }
        __syncthreads();
    }
    #pragma unroll
    for (int mi = 0; mi < 2; ++mi)
        #pragma unroll
        for (int ni = 0; ni < 4; ++ni)
            wmma::store_matrix_sync(
                Sb + (size_t)(m0 + wm * 32 + mi * 16) * TENC + n0 + wn * 64 + ni * 16,
                Cc[mi][ni], TENC, wmma::mem_row_major);
}

// ---------------- softmax -> attn hi/lo (R12 version) ----------------
__global__ void __launch_bounds__(256) k_softmax(
    const float* __restrict__ S, __half* __restrict__ Ah, __half* __restrict__ Al)
{
    const size_t base = (size_t)blockIdx.x * TENC;
    const int tid = threadIdx.x;
    __shared__ float red[8];
    float4 v = *(const float4*)(S + base + tid * 4);
    float mx = fmaxf(fmaxf(v.x, v.y), fmaxf(v.z, v.w));
    #pragma unroll
    for (int o = 16; o > 0; o >>= 1) mx = fmaxf(mx, __shfl_xor_sync(0xffffffffu, mx, o));
    if ((tid & 31) == 0) red[tid >> 5] = mx;
    __syncthreads();
    mx = fmaxf(fmaxf(fmaxf(red[0], red[1]), fmaxf(red[2], red[3])),
               fmaxf(fmaxf(red[4], red[5]), fmaxf(red[6], red[7])));
    __syncthreads();
    v.x = __expf(v.x - mx); v.y = __expf(v.y - mx);
    v.z = __expf(v.z - mx); v.w = __expf(v.w - mx);
    float sm = v.x + v.y + v.z + v.w;
    #pragma unroll
    for (int o = 16; o > 0; o >>= 1) sm += __shfl_xor_sync(0xffffffffu, sm, o);
    if ((tid & 31) == 0) red[tid >> 5] = sm;
    __syncthreads();
    sm = red[0] + red[1] + red[2] + red[3] + red[4] + red[5] + red[6] + red[7];
    float inv = 1.0f / sm;
    v.x *= inv; v.y *= inv; v.z *= inv; v.w *= inv;
    __half h[4], l[4];
    split_h(v.x, h[0], l[0]); split_h(v.y, h[1], l[1]);
    split_h(v.z, h[2], l[2]); split_h(v.w, h[3], l[3]);
    *(ulonglong1*)(Ah + base + tid * 4) = *(ulonglong1*)h;
    *(ulonglong1*)(Al + base + tid * 4) = *(ulonglong1*)l;
}

// ---------------- context: H1 = H0 + attn @ V, N-tile = 128 ----------------
#define BPAD 136
#define CXSM (256 * HPAD + 128 * BPAD)
#define EPAD2 132
__global__ void __launch_bounds__(256, 2) k_ctx_h3(
    const __half* __restrict__ AHh, const __half* __restrict__ AHl,
    const __half* __restrict__ Vh, const __half* __restrict__ Vl,
    const float* __restrict__ H0, float* __restrict__ H1, __half* __restrict__ H1H)
{
    extern __shared__ __align__(16) __half sh[];
    __half* Ah_ = sh;
    __half* Al_ = sh + 128 * HPAD;
    __half* Bh_ = sh + 256 * HPAD;
    __half* Bl_ = sh + 256 * HPAD + 64 * BPAD;
    const int tid = threadIdx.x;
    const int wid = tid >> 5;
    const int b = blockIdx.z;
    const int m0 = blockIdx.x * 128;
    const int n0 = blockIdx.y * 128;
    const int wm = wid & 3;
    const int wn = wid >> 2;
    const __half* Ahb = AHh + ((size_t)b * TDEC + m0) * TENC;
    const __half* Alb = AHl + ((size_t)b * TDEC + m0) * TENC;
    const __half* Vhb = Vh + (size_t)b * TENC * DMODEL;
    const __half* Vlb = Vl + (size_t)b * TENC * DMODEL;

    wmma::fragment<wmma::accumulator, 16, 16, 16, float> Cc[2][4];
    #pragma unroll
    for (int i = 0; i < 2; ++i)
        #pragma unroll
        for (int j = 0; j < 4; ++j) wmma::fill_fragment(Cc[i][j], 0.0f);

    for (int c = 0; c < 16; ++c) {
        const int k0 = c * 64;
        #pragma unroll
        for (int i = 0; i < 4; ++i) {
            int e = tid + i * 256;
            int r = e >> 3, q = e & 7;
            *(float4*)(Ah_ + r * HPAD + q * 8) =
                *(const float4*)(Ahb + (size_t)r * TENC + k0 + q * 8);
            *(float4*)(Al_ + r * HPAD + q * 8) =
                *(const float4*)(Alb + (size_t)r * TENC + k0 + q * 8);
        }
        #pragma unroll
        for (int i = 0; i < 4; ++i) {
            int e = tid + i * 256;
            int k = e >> 4, q = e & 15;
            *(float4*)(Bh_ + k * BPAD + q * 8) =
                *(const float4*)(Vhb + (size_t)(k0 + k) * DMODEL + n0 + q * 8);
            *(float4*)(Bl_ + k * BPAD + q * 8) =
                *(const float4*)(Vlb + (size_t)(k0 + k) * DMODEL + n0 + q * 8);
        }
        __syncthreads();
        #pragma unroll
        for (int ks = 0; ks < 4; ++ks) {
            wmma::fragment<wmma::matrix_a, 16, 16, 16, __half, wmma::row_major> afh[2], afl[2];
            #pragma unroll
            for (int mi = 0; mi < 2; ++mi) {
                wmma::load_matrix_sync(afh[mi], Ah_ + (wm * 32 + mi * 16) * HPAD + ks * 16, HPAD);
                wmma::load_matrix_sync(afl[mi], Al_ + (wm * 32 + mi * 16) * HPAD + ks * 16, HPAD);
            }
            #pragma unroll
            for (int ni = 0; ni < 4; ++ni) {
                wmma::fragment<wmma::matrix_b, 16, 16, 16, __half, wmma::row_major> bfh, bfl;
                wmma::load_matrix_sync(bfh, Bh_ + (ks * 16) * BPAD + wn * 64 + ni * 16, BPAD);
                wmma::load_matrix_sync(bfl, Bl_ + (ks * 16) * BPAD + wn * 64 + ni * 16, BPAD);
                #pragma unroll
                for (int mi = 0; mi < 2; ++mi) {
                    wmma::mma_sync(Cc[mi][ni], afh[mi], bfh, Cc[mi][ni]);
                    wmma::mma_sync(Cc[mi][ni], afh[mi], bfl, Cc[mi][ni]);
                    wmma::mma_sync(Cc[mi][ni], afl[mi], bfh, Cc[mi][ni]);
                }
            }
        }
        __syncthreads();
    }

    float* Cb = (float*)sh;
    #pragma unroll
    for (int mi = 0; mi < 2; ++mi)
        #pragma unroll
        for (int ni = 0; ni < 4; ++ni)
            wmma::store_matrix_sync(Cb + (wm * 32 + mi * 16) * EPAD2 + wn * 64 + ni * 16,
                                    Cc[mi][ni], EPAD2, wmma::mem_row_major);
    __syncthreads();
    const int r = tid >> 1;
    const int cc = (tid & 1) * 64;
    const size_t m = (size_t)b * TDEC + m0 + r;
    const float* h0r = H0 + m * DMODEL + n0 + cc;
    float* h1r = H1 + m * DMODEL + n0 + cc;
    __half* hhr = H1H + m * DMODEL + n0 + cc;
    #pragma unroll
    for (int q = 0; q < 16; ++q) {
        float4 cv = *(const float4*)(Cb + r * EPAD2 + cc + q * 4);
        float4 h0 = *(const float4*)(h0r + q * 4);
        float4 o = make_float4(cv.x + h0.x, cv.y + h0.y, cv.z + h0.z, cv.w + h0.w);
        *(float4*)(h1r + q * 4) = o;
        *(__half2*)(hhr + q * 4)     = __floats2half2_rn(o.x, o.y);
        *(__half2*)(hhr + q * 4 + 2) = __floats2half2_rn(o.z, o.w);
    }
}

// ---------------- q-GEMM h3: Q = A @ W^T + b -> Qh/Ql ----------------
__global__ void __launch_bounds__(256, 2) k_qgemm_h3(
    const __half* __restrict__ Ahg, const __half* __restrict__ Alg,
    const __half* __restrict__ Wh, const __half* __restrict__ Wl,
    const float* __restrict__ bias,
    __half* __restrict__ Oh, __half* __restrict__ Ol)
{
    extern __shared__ __align__(16) __half sh[];
    __half* Ah_ = sh;
    __half* Al_ = sh + 128 * HPAD;
    __half* Bh_ = sh + 256 * HPAD;
    __half* Bl_ = sh + 320 * HPAD;
    const int tid = threadIdx.x;
    const int wid = tid >> 5;
    const int m0 = blockIdx.x * 128;
    const int n0 = blockIdx.y * 64;
    const int wm = wid & 3;
    const int wn = wid >> 2;

    wmma::fragment<wmma::accumulator, 16, 16, 16, float> Cc[2][2];
    #pragma unroll
    for (int i = 0; i < 2; ++i)
        #pragma unroll
        for (int j = 0; j < 2; ++j) wmma::fill_fragment(Cc[i][j], 0.0f);

    for (int c = 0; c < 4; ++c) {
        const int k0 = c * 64;
        #pragma unroll
        for (int i = 0; i < 4; ++i) {
            int e = tid + i * 256;
            int r = e >> 3, q = e & 7;
            *(float4*)(Ah_ + r * HPAD + q * 8) =
                *(const float4*)(Ahg + (size_t)(m0 + r) * DMODEL + k0 + q * 8);
            *(float4*)(Al_ + r * HPAD + q * 8) =
                *(const float4*)(Alg + (size_t)(m0 + r) * DMODEL + k0 + q * 8);
        }
        #pragma unroll
        for (int i = 0; i < 2; ++i) {
            int e = tid + i * 256;
            int n = e >> 3, q = e & 7;
            *(float4*)(Bh_ + n * HPAD + q * 8) =
                *(const float4*)(Wh + (size_t)(n0 + n) * DMODEL + k0 + q * 8);
            *(float4*)(Bl_ + n * HPAD + q * 8) =
                *(const float4*)(Wl + (size_t)(n0 + n) * DMODEL + k0 + q * 8);
        }
        __syncthreads();
        #pragma unroll
        for (int ks = 0; ks < 4; ++ks) {
            wmma::fragment<wmma::matrix_a, 16, 16, 16, __half, wmma::row_major> afh[2], afl[2];
            wmma::fragment<wmma::matrix_b, 16, 16, 16, __half, wmma::col_major> bfh[2], bfl[2];
            #pragma unroll
            for (int mi = 0; mi < 2; ++mi) {
                wmma::load_matrix_sync(afh[mi], Ah_ + (wm * 32 + mi * 16) * HPAD + ks * 16, HPAD);
                wmma::load_matrix_sync(afl[mi], Al_ + (wm * 32 + mi * 16) * HPAD + ks * 16, HPAD);
            }
            #pragma unroll
            for (int ni = 0; ni < 2; ++ni) {
                wmma::load_matrix_sync(bfh[ni], Bh_ + (wn * 32 + ni * 16) * HPAD + ks * 16, HPAD);
                wmma::load_matrix_sync(bfl[ni], Bl_ + (wn * 32 + ni * 16) * HPAD + ks * 16, HPAD);
            }
            #pragma unroll
            for (int mi = 0; mi < 2; ++mi)
                #pragma unroll
                for (int ni = 0; ni < 2; ++ni) {
                    wmma::mma_sync(Cc[mi][ni], afh[mi], bfh[ni], Cc[mi][ni]);
                    wmma::mma_sync(Cc[mi][ni], afh[mi], bfl[ni], Cc[mi][ni]);
                    wmma::mma_sync(Cc[mi][ni], afl[mi], bfh[ni], Cc[mi][ni]);
                }
        }
        __syncthreads();
    }

    float* Cb = (float*)sh;
    #pragma unroll
    for (int mi = 0; mi < 2; ++mi)
        #pragma unroll
        for (int ni = 0; ni < 2; ++ni)
            wmma::store_matrix_sync(Cb + (wm * 32 + mi * 16) * EPAD + wn * 32 + ni * 16,
                                    Cc[mi][ni], EPAD, wmma::mem_row_major);
    __syncthreads();
    const int r = tid >> 1;
    const int cc = (tid & 1) * 32;
    const int m = m0 + r;
    __half* ohr = Oh + (size_t)m * DMODEL + n0 + cc;
    __half* olr = Ol + (size_t)m * DMODEL + n0 + cc;
    #pragma unroll
    for (int q = 0; q < 8; ++q) {
        float4 cv = *(const float4*)(Cb + r * EPAD + cc + q * 4);
        float4 bb = *(const float4*)(bias + n0 + cc + q * 4);
        __half h[4], l[4];
        split_h(cv.x + bb.x, h[0], l[0]); split_h(cv.y + bb.y, h[1], l[1]);
        split_h(cv.z + bb.z, h[2], l[2]); split_h(cv.w + bb.w, h[3], l[3]);
        *(ulonglong1*)(ohr + q * 4) = *(ulonglong1*)h;
        *(ulonglong1*)(olr + q * 4) = *(ulonglong1*)l;
    }
}

// ---------------- proj h3 (N=80 predicated) ----------------
__global__ void __launch_bounds__(256, 2) k_proj_h3(
    const __half* __restrict__ Ahg, const __half* __restrict__ Alg,
    const __half* __restrict__ Wh, const __half* __restrict__ Wl,
    const float* __restrict__ bias, float* __restrict__ out)
{
    extern __shared__ __align__(16) __half sh[];
    __half* Ah_ = sh;
    __half* Al_ = sh + 128 * HPAD;
    __half* Bh_ = sh + 256 * HPAD;
    __half* Bl_ = sh + 320 * HPAD;
    const int tid = threadIdx.x;
    const int wid = tid >> 5;
    const int m0 = blockIdx.x * 128;
    const int n0 = blockIdx.y * 64;
    const int wm = wid & 3;
    const int wn = wid >> 2;

    wmma::fragment<wmma::accumulator, 16, 16, 16, float> Cc[2][2];
    #pragma unroll
    for (int i = 0; i < 2; ++i)
        #pragma unroll
        for (int j = 0; j < 2; ++j) wmma::fill_fragment(Cc[i][j], 0.0f);

    for (int c = 0; c < 4; ++c) {
        const int k0 = c * 64;
        #pragma unroll
        for (int i = 0; i < 4; ++i) {
            int e = tid + i * 256;
            int r = e >> 3, q = e & 7;
            *(float4*)(Ah_ + r * HPAD + q * 8) =
                *(const float4*)(Ahg + (size_t)(m0 + r) * DMODEL + k0 + q * 8);
            *(float4*)(Al_ + r * HPAD + q * 8) =
                *(const float4*)(Alg + (size_t)(m0 + r) * DMODEL + k0 + q * 8);
        }
        #pragma unroll
        for (int i = 0; i < 2; ++i) {
            int e = tid + i * 256;
            int n = e >> 3, q = e & 7;
            int row = n0 + n;
            float4 vh = make_float4(0.f, 0.f, 0.f, 0.f);
            float4 vl = vh;
            if (row < INDIM) {
                vh = *(const float4*)(Wh + (size_t)row * DMODEL + k0 + q * 8);
                vl = *(const float4*)(Wl + (size_t)row * DMODEL + k0 + q * 8);
            }
            *(float4*)(Bh_ + n * HPAD + q * 8) = vh;
            *(float4*)(Bl_ + n * HPAD + q * 8) = vl;
        }
        __syncthreads();
        #pragma unroll
        for (int ks = 0; ks < 4; ++ks) {
            wmma::fragment<wmma::matrix_a, 16, 16, 16, __half, wmma::row_major> afh[2], afl[2];
            wmma::fragment<wmma::matrix_b, 16, 16, 16, __half, wmma::col_major> bfh[2], bfl[2];
            #pragma unroll
            for (int mi = 0; mi < 2; ++mi) {
                wmma::load_matrix_sync(afh[mi], Ah_ + (wm * 32 + mi * 16) * HPAD + ks * 16, HPAD);
                wmma::load_matrix_sync(afl[mi], Al_ + (wm * 32 + mi * 16) * HPAD + ks * 16, HPAD);
            }
            #pragma unroll
            for (int ni = 0; ni < 2; ++ni) {
                wmma::load_matrix_sync(bfh[ni], Bh_ + (wn * 32 + ni * 16) * HPAD + ks * 16, HPAD);
                wmma::load_matrix_sync(bfl[ni], Bl_ + (wn * 32 + ni * 16) * HPAD + ks * 16, HPAD);
            }
            #pragma unroll
            for (int mi = 0; mi < 2; ++mi)
                #pragma unroll
                for (int ni = 0; ni < 2; ++ni) {
                    wmma::mma_sync(Cc[mi][ni], afh[mi], bfh[ni], Cc[mi][ni]);
                    wmma::mma_sync(Cc[mi][ni], afh[mi], bfl[ni], Cc[mi][ni]);
                    wmma::mma_sync(Cc[mi][ni], afl[mi], bfh[ni], Cc[mi][ni]);
                }
        }
        __syncthreads();
    }

    float* Cb = (float*)sh;
    #pragma unroll
    for (int mi = 0; mi < 2; ++mi)
        #pragma unroll
        for (int ni = 0; ni < 2; ++ni)
            wmma::store_matrix_sync(Cb + (wm * 32 + mi * 16) * EPAD + wn * 32 + ni * 16,
                                    Cc[mi][ni], EPAD, wmma::mem_row_major);
    __syncthreads();
    const int r = tid >> 1;
    const int cc = (tid & 1) * 32;
    const int m = m0 + r;
    #pragma unroll
    for (int q = 0; q < 8; ++q) {
        int col = n0 + cc + q * 4;
        if (col < INDIM) {
            float4 cv = *(const float4*)(Cb + r * EPAD + cc + q * 4);
            float4 bb = *(const float4*)(bias + col);
            *(float4*)(out + (size_t)m * INDIM + col) =
                make_float4(cv.x + bb.x, cv.y + bb.y, cv.z + bb.z, cv.w + bb.w);
        }
    }
}

// ---------------- K1: x = shift_right(mel @ W_lin^T + b_lin); also fp16 hi copy ----------------
__global__ void __launch_bounds__(256) k_lin_shift(
    const float* __restrict__ mel, const float* __restrict__ W,
    const float* __restrict__ bias, float* __restrict__ out,
    __half* __restrict__ outH)
{
    __shared__ float As[16][128];
    __shared__ float Bs[16][64];
    const int tid = threadIdx.x;
    const int m0 = blockIdx.x * 128;
    const int n0 = blockIdx.y * 64;
    const int tx = tid & 15, ty = tid >> 4;
    u64 acc[4][4];
    #pragma unroll
    for (int i = 0; i < 4; ++i)
        #pragma unroll
        for (int j = 0; j < 4; ++j) acc[i][j] = 0ULL;

    for (int k0 = 0; k0 < INDIM; k0 += 16) {
        #pragma unroll
        for (int i = 0; i < 2; ++i) {
            int s = tid + i * 256;
            int r = s >> 2, kq = (s & 3) << 2;
            int m = m0 + r;
            int t = m & (TDEC - 1);
            float4 v = make_float4(0.f, 0.f, 0.f, 0.f);
            if (t > 0) v = *(const float4*)(mel + (size_t)(m - 1) * INDIM + k0 + kq);
            As[kq + 0][r] = v.x; As[kq + 1][r] = v.y; As[kq + 2][r] = v.z; As[kq + 3][r] = v.w;
        }
        {
            int n = tid >> 2, kq = (tid & 3) << 2;
            float4 v = *(const float4*)(W + (size_t)(n0 + n) * INDIM + k0 + kq);
            Bs[kq + 0][n] = v.x; Bs[kq + 1][n] = v.y; Bs[kq + 2][n] = v.z; Bs[kq + 3][n] = v.w;
        }
        __syncthreads();
        #pragma unroll
        for (int k = 0; k < 16; ++k) {
            ulonglong2 aa0 = *(const ulonglong2*)&As[k][ty * 8];
            ulonglong2 aa1 = *(const ulonglong2*)&As[k][ty * 8 + 4];
            float4 br = *(const float4*)&Bs[k][tx * 4];
            u64 b0 = pack_dup(br.x), b1 = pack_dup(br.y), b2 = pack_dup(br.z), b3 = pack_dup(br.w);
            ffma2(acc[0][0], aa0.x, b0); ffma2(acc[0][1], aa0.x, b1);
            ffma2(acc[0][2], aa0.x, b2); ffma2(acc[0][3], aa0.x, b3);
            ffma2(acc[1][0], aa0.y, b0); ffma2(acc[1][1], aa0.y, b1);
            ffma2(acc[1][2], aa0.y, b2); ffma2(acc[1][3], aa0.y, b3);
            ffma2(acc[2][0], aa1.x, b0); ffma2(acc[2][1], aa1.x, b1);
            ffma2(acc[2][2], aa1.x, b2); ffma2(acc[2][3], aa1.x, b3);
            ffma2(acc[3][0], aa1.y, b0); ffma2(acc[3][1], aa1.y, b1);
            ffma2(acc[3][2], aa1.y, b2); ffma2(acc[3][3], aa1.y, b3);
        }
        __syncthreads();
    }
    float4 bb = *(const float4*)(bias + n0 + tx * 4);
    #pragma unroll
    for (int i2 = 0; i2 < 4; ++i2) {
        float2 c0 = unpk(acc[i2][0]), c1 = unpk(acc[i2][1]);
        float2 c2 = unpk(acc[i2][2]), c3 = unpk(acc[i2][3]);
        int m = m0 + ty * 8 + 2 * i2;
        #pragma unroll
        for (int h = 0; h < 2; ++h) {
            int mm = m + h;
            int t = mm & (TDEC - 1);
            float4 o;
            if (t == 0) o = make_float4(0.f, 0.f, 0.f, 0.f);
            else if (h == 0)
                o = make_float4(c0.x + bb.x, c1.x + bb.y, c2.x + bb.z, c3.x + bb.w);
            else
                o = make_float4(c0.y + bb.x, c1.y + bb.y, c2.y + bb.z, c3.y + bb.w);
            *(float4*)(out + (size_t)mm * DMODEL + n0 + tx * 4) = o;
            __half* hp = outH + (size_t)mm * DMODEL + n0 + tx * 4;
            *(__half2*)(hp)     = __floats2half2_rn(o.x, o.y);
            *(__half2*)(hp + 2) = __floats2half2_rn(o.z, o.w);
        }
    }
}

// ---------------- launch ----------------
extern "C" void kernel_launch(void* const* d_in, const int* in_sizes, int n_in,
                              void* d_out, int out_size)
{
    (void)in_sizes; (void)n_in; (void)out_size;
    const float* enc   = (const float*)d_in[0];
    const float* first = (const float*)d_in[1];
    const float* mel   = (const float*)d_in[2];
    const float* W_lin = (const float*)d_in[3];
    const float* b_lin = (const float*)d_in[4];
    const float* cw0   = (const float*)d_in[5];
    const float* cb0   = (const float*)d_in[6];
    const float* cw1   = (const float*)d_in[7];
    const float* cb1   = (const float*)d_in[8];
    const float* W_att = (const float*)d_in[9];
    const float* b_att = (const float*)d_in[10];
    const float* W_prj = (const float*)d_in[11];
    const float* b_prj = (const float*)d_in[12];
    float* out = (float*)d_out;

    float *X, *H0, *H1, *S;
    __half *XH, *H0h, *H0l, *Qh, *Ql, *AHh, *AHl, *EHh, *EHl, *VHh, *VHl;
    __half *WbH0, *WbH1, *WAh, *WAl, *WPh, *WPl;
    cudaGetSymbolAddress((void**)&X,  g_X);
    cudaGetSymbolAddress((void**)&H0, g_H0);
    cudaGetSymbolAddress((void**)&H1, g_H1);
    cudaGetSymbolAddress((void**)&S,  g_S);
    cudaGetSymbolAddress((void**)&XH, g_XH);
    cudaGetSymbolAddress((void**)&H0h, g_H0h);
    cudaGetSymbolAddress((void**)&H0l, g_H0l);
    cudaGetSymbolAddress((void**)&Qh, g_Qh);
    cudaGetSymbolAddress((void**)&Ql, g_Ql);
    cudaGetSymbolAddress((void**)&AHh, g_AHh);
    cudaGetSymbolAddress((void**)&AHl, g_AHl);
    cudaGetSymbolAddress((void**)&EHh, g_EHh);
    cudaGetSymbolAddress((void**)&EHl, g_EHl);
    cudaGetSymbolAddress((void**)&VHh, g_VHh);
    cudaGetSymbolAddress((void**)&VHl, g_VHl);
    cudaGetSymbolAddress((void**)&WbH0, g_WbH0);
    cudaGetSymbolAddress((void**)&WbH1, g_WbH1);
    cudaGetSymbolAddress((void**)&WAh, g_WAh);
    cudaGetSymbolAddress((void**)&WAl, g_WAl);
    cudaGetSymbolAddress((void**)&WPh, g_WPh);
    cudaGetSymbolAddress((void**)&WPl, g_WPl);

    const int CONV_SMEM = SMH * 2;    // 36864 B
    const int H3_SMEM   = H3SM * 2;   // 55296 B
    const int SC_SMEM   = SCSM * 2;   // 73728 B
    const int CX_SMEM   = CXSM * 2;   // 71680 B
    cudaFuncSetAttribute(k_conv_wmma, cudaFuncAttributeMaxDynamicSharedMemorySize, CONV_SMEM);
    cudaFuncSetAttribute(k_scores_h3, cudaFuncAttributeMaxDynamicSharedMemorySize, SC_SMEM);
    cudaFuncSetAttribute(k_ctx_h3,    cudaFuncAttributeMaxDynamicSharedMemorySize, CX_SMEM);
    cudaFuncSetAttribute(k_qgemm_h3,  cudaFuncAttributeMaxDynamicSharedMemorySize, H3_SMEM);
    cudaFuncSetAttribute(k_proj_h3,   cudaFuncAttributeMaxDynamicSharedMemorySize, H3_SMEM);

    k_repack_nk<<<(C2 * DMODEL * 5 + 255) / 256, 256>>>(cw0, WbH0);
    k_repack_nk<<<(C2 * DMODEL * 5 + 255) / 256, 256>>>(cw1, WbH1);
    k_prep_enc<<<(BDIM * TENC * DMODEL / 4) / 256, 256>>>(enc, first, EHh, EHl, VHh, VHl);
    k_split<<<(DMODEL * DMODEL / 4) / 256, 256>>>(W_att, WAh, WAl);
    k_split<<<(INDIM * DMODEL / 4) / 256, 256>>>(W_prj, WPh, WPl);
    k_lin_shift<<<dim3(MTOT / 128, DMODEL / 64), 256>>>(mel, W_lin, b_lin, X, XH);
    k_conv_wmma<<<dim3(MTOT / 128, DMODEL / 64), 256, CONV_SMEM>>>(
        X, XH, WbH0, cb0, H0, H0h, H0l, 1);
    k_qgemm_h3<<<dim3(MTOT / 128, DMODEL / 64), 256, H3_SMEM>>>(
        H0h, H0l, WAh, WAl, b_att, Qh, Ql);
    k_scores_h3<<<dim3(TDEC / 128, TENC / 128, BDIM), 256, SC_SMEM>>>(Qh, Ql, EHh, EHl, S);
    k_softmax<<<MTOT, 256>>>(S, AHh, AHl);
    k_ctx_h3<<<dim3(TDEC / 128, DMODEL / 128, BDIM), 256, CX_SMEM>>>(
        AHh, AHl, VHh, VHl, H0, H1, XH);
    k_conv_wmma<<<dim3(MTOT / 128, DMODEL / 64), 256, CONV_SMEM>>>(
        H1, XH, WbH1, cb1, X, H0h, H0l, 0);
    k_proj_h3<<<dim3(MTOT / 128, 2), 256, H3_SMEM>>>(H0h, H0l, WPh, WPl, b_prj, out);
}

// round 16
// speedup vs baseline: 1.0308x; 1.0127x over previous
#include <cuda_runtime.h>
#include <cuda_fp16.h>
#include <math.h>
#include <stdint.h>
#include <mma.h>

using namespace nvcuda;

#define BDIM   32
#define TENC   1024
#define TDEC   2048
#define DMODEL 256
#define INDIM  80
#define C2     512
#define MTOT   (BDIM*TDEC)
#define RSQRT2 0.70710678118654752440f

typedef unsigned long long u64;

// ---------------- scratch ----------------
__device__ float  g_X [(size_t)MTOT*DMODEL];
__device__ float  g_H0[(size_t)MTOT*DMODEL];
__device__ float  g_H1[(size_t)MTOT*DMODEL];
__device__ __half g_XH[(size_t)MTOT*DMODEL];
__device__ __half g_H0h[(size_t)MTOT*DMODEL];
__device__ __half g_H0l[(size_t)MTOT*DMODEL];
__device__ __half g_Qh[(size_t)MTOT*DMODEL];
__device__ __half g_Ql[(size_t)MTOT*DMODEL];
__device__ float  g_S [(size_t)BDIM*TDEC*TENC];
__device__ __half g_AHh[(size_t)BDIM*TDEC*TENC];
__device__ __half g_AHl[(size_t)BDIM*TDEC*TENC];
__device__ __half g_EHh[(size_t)BDIM*TENC*DMODEL];
__device__ __half g_EHl[(size_t)BDIM*TENC*DMODEL];
__device__ __half g_VHh[(size_t)BDIM*TENC*DMODEL];
__device__ __half g_VHl[(size_t)BDIM*TENC*DMODEL];
__device__ __half g_WbH0[(size_t)C2*1280];
__device__ __half g_WbH1[(size_t)C2*1280];
__device__ __half g_WAh[(size_t)DMODEL*DMODEL];
__device__ __half g_WAl[(size_t)DMODEL*DMODEL];
__device__ __half g_WPh[(size_t)INDIM*DMODEL];
__device__ __half g_WPl[(size_t)INDIM*DMODEL];

__device__ __forceinline__ float sigf(float x) { return 1.0f / (1.0f + __expf(-x)); }
__device__ __forceinline__ void split_h(float x, __half &hi, __half &lo) {
    hi = __float2half_rn(x);
    lo = __float2half_rn(x - __half2float(hi));
}

// ------- packed f32x2 helpers (lin_shift only) -------
__device__ __forceinline__ u64 pack_dup(float x) {
    u64 r; asm("mov.b64 %0, {%1, %1};" : "=l"(r) : "f"(x)); return r;
}
__device__ __forceinline__ void ffma2(u64 &d, u64 a, u64 b) {
    asm("fma.rn.f32x2 %0, %1, %2, %0;" : "+l"(d) : "l"(a), "l"(b));
}
__device__ __forceinline__ float2 unpk(u64 v) {
    float lo, hi; asm("mov.b64 {%0, %1}, %2;" : "=f"(lo), "=f"(hi) : "l"(v));
    return make_float2(lo, hi);
}

// ---------------- weight repack + fp16 round ----------------
__global__ void __launch_bounds__(256) k_repack_nk(const float* __restrict__ w,
                                                   __half* __restrict__ wb)
{
    int i = blockIdx.x * 256 + threadIdx.x;
    if (i >= C2 * DMODEL * 5) return;
    int n   = i / (DMODEL * 5);
    int rem = i - n * (DMODEL * 5);
    int ch  = rem / 5;
    int tap = rem - ch * 5;
    wb[(size_t)n * 1280 + tap * DMODEL + ch] = __float2half_rn(w[i]);
}

// ---------------- enc/V prep ----------------
__global__ void __launch_bounds__(256) k_prep_enc(
    const float* __restrict__ enc, const float* __restrict__ first,
    __half* __restrict__ Eh, __half* __restrict__ El,
    __half* __restrict__ Vh, __half* __restrict__ Vl)
{
    size_t i = (size_t)blockIdx.x * 256 + threadIdx.x;
    float4 e = *(const float4*)(enc + i * 4);
    float4 f = *(const float4*)(first + i * 4);
    __half eh[4], el[4], vh[4], vl[4];
    split_h(e.x, eh[0], el[0]); split_h(e.y, eh[1], el[1]);
    split_h(e.z, eh[2], el[2]); split_h(e.w, eh[3], el[3]);
    split_h(e.x + f.x, vh[0], vl[0]); split_h(e.y + f.y, vh[1], vl[1]);
    split_h(e.z + f.z, vh[2], vl[2]); split_h(e.w + f.w, vh[3], vl[3]);
    *(ulonglong1*)(Eh + i * 4) = *(ulonglong1*)eh;
    *(ulonglong1*)(El + i * 4) = *(ulonglong1*)el;
    *(ulonglong1*)(Vh + i * 4) = *(ulonglong1*)vh;
    *(ulonglong1*)(Vl + i * 4) = *(ulonglong1*)vl;
}

// ---------------- fp32 -> hi/lo split (weights only) ----------------
__global__ void __launch_bounds__(256) k_split(
    const float* __restrict__ x, __half* __restrict__ hi, __half* __restrict__ lo)
{
    size_t i = (size_t)blockIdx.x * 256 + threadIdx.x;
    float4 v = *(const float4*)(x + i * 4);
    __half h[4], l[4];
    split_h(v.x, h[0], l[0]); split_h(v.y, h[1], l[1]);
    split_h(v.z, h[2], l[2]); split_h(v.w, h[3], l[3]);
    *(ulonglong1*)(hi + i * 4) = *(ulonglong1*)h;
    *(ulonglong1*)(lo + i * 4) = *(ulonglong1*)l;
}

// ================= conv: fp16 wmma single-buffer + hi/lo epilogue (R15-proven) =================
#define CPADH 72
#define SMH   (256*CPADH)
#define EPAD  68
__global__ void __launch_bounds__(256, 2) k_conv_wmma(
    const float* __restrict__ Xres, const __half* __restrict__ XH,
    const __half* __restrict__ Wb, const float* __restrict__ bias,
    float* __restrict__ out, __half* __restrict__ outH, __half* __restrict__ outL,
    int writeF32)
{
    extern __shared__ __align__(16) __half smh[];
    __half* As = smh;
    __half* Bh = smh + 128 * CPADH;
    const int tid = threadIdx.x;
    const int wid = tid >> 5;
    const int m0 = blockIdx.x * 128;
    const int n0 = blockIdx.y * 64;
    const int wm = wid & 3;
    const int wn = wid >> 2;

    wmma::fragment<wmma::accumulator, 16, 16, 16, float> Ca[2][2], Cg[2][2];
    #pragma unroll
    for (int i = 0; i < 2; ++i)
        #pragma unroll
        for (int j = 0; j < 2; ++j) {
            wmma::fill_fragment(Ca[i][j], 0.0f);
            wmma::fill_fragment(Cg[i][j], 0.0f);
        }

    for (int c = 0; c < 20; ++c) {
        const int tap = c >> 2;
        const int ch0 = (c & 3) << 6;
        #pragma unroll
        for (int i = 0; i < 4; ++i) {
            int e = tid + i * 256;
            int r = e >> 3, q = e & 7;
            int t = (m0 + r) & (TDEC - 1);
            float4 v = make_float4(0.f, 0.f, 0.f, 0.f);
            if (t + tap - 4 >= 0)
                v = *(const float4*)(XH + (size_t)(m0 + r + tap - 4) * DMODEL + ch0 + q * 8);
            *(float4*)(As + r * CPADH + q * 8) = v;
        }
        #pragma unroll
        for (int i = 0; i < 4; ++i) {
            int e = tid + i * 256;
            int n = e >> 3, q = e & 7;
            int row = (n < 64) ? (n0 + n) : (n0 + 256 + n - 64);
            float4 v = *(const float4*)(Wb + (size_t)row * 1280 + tap * DMODEL + ch0 + q * 8);
            *(float4*)(Bh + n * CPADH + q * 8) = v;
        }
        __syncthreads();
        #pragma unroll
        for (int ks = 0; ks < 4; ++ks) {
            wmma::fragment<wmma::matrix_a, 16, 16, 16, __half, wmma::row_major> af[2];
            wmma::fragment<wmma::matrix_b, 16, 16, 16, __half, wmma::col_major> bfa[2], bfg[2];
            #pragma unroll
            for (int mi = 0; mi < 2; ++mi)
                wmma::load_matrix_sync(af[mi], As + (wm * 32 + mi * 16) * CPADH + ks * 16, CPADH);
            #pragma unroll
            for (int ni = 0; ni < 2; ++ni) {
                wmma::load_matrix_sync(bfa[ni], Bh + (wn * 32 + ni * 16) * CPADH + ks * 16, CPADH);
                wmma::load_matrix_sync(bfg[ni], Bh + (64 + wn * 32 + ni * 16) * CPADH + ks * 16, CPADH);
            }
            #pragma unroll
            for (int mi = 0; mi < 2; ++mi)
                #pragma unroll
                for (int ni = 0; ni < 2; ++ni) {
                    wmma::mma_sync(Ca[mi][ni], af[mi], bfa[ni], Ca[mi][ni]);
                    wmma::mma_sync(Cg[mi][ni], af[mi], bfg[ni], Cg[mi][ni]);
                }
        }
        __syncthreads();
    }

    float* Cb = (float*)smh;
    #pragma unroll
    for (int mi = 0; mi < 2; ++mi)
        #pragma unroll
        for (int ni = 0; ni < 2; ++ni)
            wmma::store_matrix_sync(Cb + (wm * 32 + mi * 16) * EPAD + wn * 32 + ni * 16,
                                    Ca[mi][ni], EPAD, wmma::mem_row_major);
    __syncthreads();
    const int r = tid >> 1;
    const int cc = (tid & 1) * 32;
    float av[32];
    #pragma unroll
    for (int q = 0; q < 8; ++q)
        *(float4*)&av[q * 4] = *(const float4*)(Cb + r * EPAD + cc + q * 4);
    __syncthreads();
    #pragma unroll
    for (int mi = 0; mi < 2; ++mi)
        #pragma unroll
        for (int ni = 0; ni < 2; ++ni)
            wmma::store_matrix_sync(Cb + (wm * 32 + mi * 16) * EPAD + wn * 32 + ni * 16,
                                    Cg[mi][ni], EPAD, wmma::mem_row_major);
    __syncthreads();
    {
        const int m = m0 + r;
        const float* xr = Xres + (size_t)m * DMODEL + n0 + cc;
        float* orow = out + (size_t)m * DMODEL + n0 + cc;
        __half* ohr = outH + (size_t)m * DMODEL + n0 + cc;
        __half* olr = outL + (size_t)m * DMODEL + n0 + cc;
        #pragma unroll
        for (int q = 0; q < 8; ++q) {
            float4 g = *(const float4*)(Cb + r * EPAD + cc + q * 4);
            float4 res = *(const float4*)(xr + q * 4);
            float4 ba = *(const float4*)(bias + n0 + cc + q * 4);
            float4 bg = *(const float4*)(bias + 256 + n0 + cc + q * 4);
            float4 o;
            o.x = fmaf(av[q*4+0] + ba.x, sigf(g.x + bg.x), res.x) * RSQRT2;
            o.y = fmaf(av[q*4+1] + ba.y, sigf(g.y + bg.y), res.y) * RSQRT2;
            o.z = fmaf(av[q*4+2] + ba.z, sigf(g.z + bg.z), res.z) * RSQRT2;
            o.w = fmaf(av[q*4+3] + ba.w, sigf(g.w + bg.w), res.w) * RSQRT2;
            if (writeF32) *(float4*)(orow + q * 4) = o;
            __half h[4], l[4];
            split_h(o.x, h[0], l[0]); split_h(o.y, h[1], l[1]);
            split_h(o.z, h[2], l[2]); split_h(o.w, h[3], l[3]);
            *(ulonglong1*)(ohr + q * 4) = *(ulonglong1*)h;
            *(ulonglong1*)(olr + q * 4) = *(ulonglong1*)l;
        }
    }
}

// ================= h3 kernels (R12-proven) =================
#define HPAD 72
#define H3SM ((256 + 128) * HPAD)

// ---------------- scores: S = Q @ enc^T (per batch), N-tile = 128 ----------------
#define SCSM (512 * HPAD)
__global__ void __launch_bounds__(256, 2) k_scores_h3(
    const __half* __restrict__ Qh, const __half* __restrict__ Ql,
    const __half* __restrict__ Eh, const __half* __restrict__ El,
    float* __restrict__ S)
{
    extern __shared__ __align__(16) __half sh[];
    __half* Ah_ = sh;
    __half* Al_ = sh + 128 * HPAD;
    __half* Bh_ = sh + 256 * HPAD;
    __half* Bl_ = sh + 384 * HPAD;
    const int tid = threadIdx.x;
    const int wid = tid >> 5;
    const int b = blockIdx.z;
    const int m0 = blockIdx.x * 128;
    const int n0 = blockIdx.y * 128;
    const int wm = wid & 3;
    const int wn = wid >> 2;
    const __half* Qhb = Qh + ((size_t)b * TDEC + m0) * DMODEL;
    const __half* Qlb = Ql + ((size_t)b * TDEC + m0) * DMODEL;
    const __half* Ehb = Eh + ((size_t)b * TENC + n0) * DMODEL;
    const __half* Elb = El + ((size_t)b * TENC + n0) * DMODEL;
    float* Sb = S + (size_t)b * TDEC * TENC;

    wmma::fragment<wmma::accumulator, 16, 16, 16, float> Cc[2][4];
    #pragma unroll
    for (int i = 0; i < 2; ++i)
        #pragma unroll
        for (int j = 0; j < 4; ++j) wmma::fill_fragment(Cc[i][j], 0.0f);

    for (int c = 0; c < 4; ++c) {
        const int k0 = c * 64;
        #pragma unroll
        for (int i = 0; i < 4; ++i) {
            int e = tid + i * 256;
            int r = e >> 3, q = e & 7;
            *(float4*)(Ah_ + r * HPAD + q * 8) =
                *(const float4*)(Qhb + (size_t)r * DMODEL + k0 + q * 8);
            *(float4*)(Al_ + r * HPAD + q * 8) =
                *(const float4*)(Qlb + (size_t)r * DMODEL + k0 + q * 8);
        }
        #pragma unroll
        for (int i = 0; i < 4; ++i) {
            int e = tid + i * 256;
            int r = e >> 3, q = e & 7;
            *(float4*)(Bh_ + r * HPAD + q * 8) =
                *(const float4*)(Ehb + (size_t)r * DMODEL + k0 + q * 8);
            *(float4*)(Bl_ + r * HPAD + q * 8) =
                *(const float4*)(Elb + (size_t)r * DMODEL + k0 + q * 8);
        }
        __syncthreads();
        #pragma unroll
        for (int ks = 0; ks < 4; ++ks) {
            wmma::fragment<wmma::matrix_a, 16, 16, 16, __half, wmma::row_major> afh[2], afl[2];
            #pragma unroll
            for (int mi = 0; mi < 2; ++mi) {
                wmma::load_matrix_sync(afh[mi], Ah_ + (wm * 32 + mi * 16) * HPAD + ks * 16, HPAD);
                wmma::load_matrix_sync(afl[mi], Al_ + (wm * 32 + mi * 16) * HPAD + ks * 16, HPAD);
            }
            #pragma unroll
            for (int ni = 0; ni < 4; ++ni) {
                wmma::fragment<wmma::matrix_b, 16, 16, 16, __half, wmma::col_major> bfh, bfl;
                wmma::load_matrix_sync(bfh, Bh_ + (wn * 64 + ni * 16) * HPAD + ks * 16, HPAD);
                wmma::load_matrix_sync(bfl, Bl_ + (wn * 64 + ni * 16) * HPAD + ks * 16, HPAD);
                #pragma unroll
                for (int mi = 0; mi < 2; ++mi) {
                    wmma::mma_sync(Cc[mi][ni], afh[mi], bfh, Cc[mi][ni]);
                    wmma::mma_sync(Cc[mi][ni], afh[mi], bfl, Cc[mi][ni]);
                    wmma::mma_sync(Cc[mi][ni], afl[mi], bfh, Cc[mi][ni]);
                }
            }
        }
        __syncthreads();
    }
    #pragma unroll
    for (int mi = 0; mi < 2; ++mi)
        #pragma unroll
        for (int ni = 0; ni < 4; ++ni)
            wmma::store_matrix_sync(
                Sb + (size_t)(m0 + wm * 32 + mi * 16) * TENC + n0 + wn * 64 + ni * 16,
                Cc[mi][ni], TENC, wmma::mem_row_major);
}

// ---------------- softmax: 2 rows/CTA, 2 outstanding loads/thread ----------------
__global__ void __launch_bounds__(256) k_softmax(
    const float* __restrict__ S, __half* __restrict__ Ah, __half* __restrict__ Al)
{
    const int tid = threadIdx.x;
    const int half = tid >> 7;           // 0/1 (warp-aligned halves)
    const int rt = tid & 127;
    const int wid = tid >> 5;            // 0..7
    const size_t base = ((size_t)blockIdx.x * 2 + half) * TENC;
    __shared__ float red1[8], red2[8];

    float4 v1 = *(const float4*)(S + base + rt * 4);
    float4 v2 = *(const float4*)(S + base + 512 + rt * 4);
    float mx = fmaxf(fmaxf(fmaxf(v1.x, v1.y), fmaxf(v1.z, v1.w)),
                     fmaxf(fmaxf(v2.x, v2.y), fmaxf(v2.z, v2.w)));
    #pragma unroll
    for (int o = 16; o > 0; o >>= 1) mx = fmaxf(mx, __shfl_xor_sync(0xffffffffu, mx, o));
    if ((tid & 31) == 0) red1[wid] = mx;
    __syncthreads();
    {
        int b0 = half * 4;
        mx = fmaxf(fmaxf(red1[b0], red1[b0 + 1]), fmaxf(red1[b0 + 2], red1[b0 + 3]));
    }
    v1.x = __expf(v1.x - mx); v1.y = __expf(v1.y - mx);
    v1.z = __expf(v1.z - mx); v1.w = __expf(v1.w - mx);
    v2.x = __expf(v2.x - mx); v2.y = __expf(v2.y - mx);
    v2.z = __expf(v2.z - mx); v2.w = __expf(v2.w - mx);
    float sm = v1.x + v1.y + v1.z + v1.w + v2.x + v2.y + v2.z + v2.w;
    #pragma unroll
    for (int o = 16; o > 0; o >>= 1) sm += __shfl_xor_sync(0xffffffffu, sm, o);
    if ((tid & 31) == 0) red2[wid] = sm;
    __syncthreads();
    {
        int b0 = half * 4;
        sm = red2[b0] + red2[b0 + 1] + red2[b0 + 2] + red2[b0 + 3];
    }
    float inv = 1.0f / sm;
    v1.x *= inv; v1.y *= inv; v1.z *= inv; v1.w *= inv;
    v2.x *= inv; v2.y *= inv; v2.z *= inv; v2.w *= inv;
    __half h1[4], l1[4], h2[4], l2[4];
    split_h(v1.x, h1[0], l1[0]); split_h(v1.y, h1[1], l1[1]);
    split_h(v1.z, h1[2], l1[2]); split_h(v1.w, h1[3], l1[3]);
    split_h(v2.x, h2[0], l2[0]); split_h(v2.y, h2[1], l2[1]);
    split_h(v2.z, h2[2], l2[2]); split_h(v2.w, h2[3], l2[3]);
    *(ulonglong1*)(Ah + base + rt * 4)       = *(ulonglong1*)h1;
    *(ulonglong1*)(Ah + base + 512 + rt * 4) = *(ulonglong1*)h2;
    *(ulonglong1*)(Al + base + rt * 4)       = *(ulonglong1*)l1;
    *(ulonglong1*)(Al + base + 512 + rt * 4) = *(ulonglong1*)l2;
}

// ---------------- context: H1 = H0 + attn @ V, N-tile = 128 ----------------
#define BPAD 136
#define CXSM (256 * HPAD + 128 * BPAD)
#define EPAD2 132
__global__ void __launch_bounds__(256, 2) k_ctx_h3(
    const __half* __restrict__ AHh, const __half* __restrict__ AHl,
    const __half* __restrict__ Vh, const __half* __restrict__ Vl,
    const float* __restrict__ H0, float* __restrict__ H1, __half* __restrict__ H1H)
{
    extern __shared__ __align__(16) __half sh[];
    __half* Ah_ = sh;
    __half* Al_ = sh + 128 * HPAD;
    __half* Bh_ = sh + 256 * HPAD;
    __half* Bl_ = sh + 256 * HPAD + 64 * BPAD;
    const int tid = threadIdx.x;
    const int wid = tid >> 5;
    const int b = blockIdx.z;
    const int m0 = blockIdx.x * 128;
    const int n0 = blockIdx.y * 128;
    const int wm = wid & 3;
    const int wn = wid >> 2;
    const __half* Ahb = AHh + ((size_t)b * TDEC + m0) * TENC;
    const __half* Alb = AHl + ((size_t)b * TDEC + m0) * TENC;
    const __half* Vhb = Vh + (size_t)b * TENC * DMODEL;
    const __half* Vlb = Vl + (size_t)b * TENC * DMODEL;

    wmma::fragment<wmma::accumulator, 16, 16, 16, float> Cc[2][4];
    #pragma unroll
    for (int i = 0; i < 2; ++i)
        #pragma unroll
        for (int j = 0; j < 4; ++j) wmma::fill_fragment(Cc[i][j], 0.0f);

    for (int c = 0; c < 16; ++c) {
        const int k0 = c * 64;
        #pragma unroll
        for (int i = 0; i < 4; ++i) {
            int e = tid + i * 256;
            int r = e >> 3, q = e & 7;
            *(float4*)(Ah_ + r * HPAD + q * 8) =
                *(const float4*)(Ahb + (size_t)r * TENC + k0 + q * 8);
            *(float4*)(Al_ + r * HPAD + q * 8) =
                *(const float4*)(Alb + (size_t)r * TENC + k0 + q * 8);
        }
        #pragma unroll
        for (int i = 0; i < 4; ++i) {
            int e = tid + i * 256;
            int k = e >> 4, q = e & 15;
            *(float4*)(Bh_ + k * BPAD + q * 8) =
                *(const float4*)(Vhb + (size_t)(k0 + k) * DMODEL + n0 + q * 8);
            *(float4*)(Bl_ + k * BPAD + q * 8) =
                *(const float4*)(Vlb + (size_t)(k0 + k) * DMODEL + n0 + q * 8);
        }
        __syncthreads();
        #pragma unroll
        for (int ks = 0; ks < 4; ++ks) {
            wmma::fragment<wmma::matrix_a, 16, 16, 16, __half, wmma::row_major> afh[2], afl[2];
            #pragma unroll
            for (int mi = 0; mi < 2; ++mi) {
                wmma::load_matrix_sync(afh[mi], Ah_ + (wm * 32 + mi * 16) * HPAD + ks * 16, HPAD);
                wmma::load_matrix_sync(afl[mi], Al_ + (wm * 32 + mi * 16) * HPAD + ks * 16, HPAD);
            }
            #pragma unroll
            for (int ni = 0; ni < 4; ++ni) {
                wmma::fragment<wmma::matrix_b, 16, 16, 16, __half, wmma::row_major> bfh, bfl;
                wmma::load_matrix_sync(bfh, Bh_ + (ks * 16) * BPAD + wn * 64 + ni * 16, BPAD);
                wmma::load_matrix_sync(bfl, Bl_ + (ks * 16) * BPAD + wn * 64 + ni * 16, BPAD);
                #pragma unroll
                for (int mi = 0; mi < 2; ++mi) {
                    wmma::mma_sync(Cc[mi][ni], afh[mi], bfh, Cc[mi][ni]);
                    wmma::mma_sync(Cc[mi][ni], afh[mi], bfl, Cc[mi][ni]);
                    wmma::mma_sync(Cc[mi][ni], afl[mi], bfh, Cc[mi][ni]);
                }
            }
        }
        __syncthreads();
    }

    float* Cb = (float*)sh;
    #pragma unroll
    for (int mi = 0; mi < 2; ++mi)
        #pragma unroll
        for (int ni = 0; ni < 4; ++ni)
            wmma::store_matrix_sync(Cb + (wm * 32 + mi * 16) * EPAD2 + wn * 64 + ni * 16,
                                    Cc[mi][ni], EPAD2, wmma::mem_row_major);
    __syncthreads();
    const int r = tid >> 1;
    const int cc = (tid & 1) * 64;
    const size_t m = (size_t)b * TDEC + m0 + r;
    const float* h0r = H0 + m * DMODEL + n0 + cc;
    float* h1r = H1 + m * DMODEL + n0 + cc;
    __half* hhr = H1H + m * DMODEL + n0 + cc;
    #pragma unroll
    for (int q = 0; q < 16; ++q) {
        float4 cv = *(const float4*)(Cb + r * EPAD2 + cc + q * 4);
        float4 h0 = *(const float4*)(h0r + q * 4);
        float4 o = make_float4(cv.x + h0.x, cv.y + h0.y, cv.z + h0.z, cv.w + h0.w);
        *(float4*)(h1r + q * 4) = o;
        *(__half2*)(hhr + q * 4)     = __floats2half2_rn(o.x, o.y);
        *(__half2*)(hhr + q * 4 + 2) = __floats2half2_rn(o.z, o.w);
    }
}

// ---------------- q-GEMM h3: Q = A @ W^T + b -> Qh/Ql ----------------
__global__ void __launch_bounds__(256, 2) k_qgemm_h3(
    const __half* __restrict__ Ahg, const __half* __restrict__ Alg,
    const __half* __restrict__ Wh, const __half* __restrict__ Wl,
    const float* __restrict__ bias,
    __half* __restrict__ Oh, __half* __restrict__ Ol)
{
    extern __shared__ __align__(16) __half sh[];
    __half* Ah_ = sh;
    __half* Al_ = sh + 128 * HPAD;
    __half* Bh_ = sh + 256 * HPAD;
    __half* Bl_ = sh + 320 * HPAD;
    const int tid = threadIdx.x;
    const int wid = tid >> 5;
    const int m0 = blockIdx.x * 128;
    const int n0 = blockIdx.y * 64;
    const int wm = wid & 3;
    const int wn = wid >> 2;

    wmma::fragment<wmma::accumulator, 16, 16, 16, float> Cc[2][2];
    #pragma unroll
    for (int i = 0; i < 2; ++i)
        #pragma unroll
        for (int j = 0; j < 2; ++j) wmma::fill_fragment(Cc[i][j], 0.0f);

    for (int c = 0; c < 4; ++c) {
        const int k0 = c * 64;
        #pragma unroll
        for (int i = 0; i < 4; ++i) {
            int e = tid + i * 256;
            int r = e >> 3, q = e & 7;
            *(float4*)(Ah_ + r * HPAD + q * 8) =
                *(const float4*)(Ahg + (size_t)(m0 + r) * DMODEL + k0 + q * 8);
            *(float4*)(Al_ + r * HPAD + q * 8) =
                *(const float4*)(Alg + (size_t)(m0 + r) * DMODEL + k0 + q * 8);
        }
        #pragma unroll
        for (int i = 0; i < 2; ++i) {
            int e = tid + i * 256;
            int n = e >> 3, q = e & 7;
            *(float4*)(Bh_ + n * HPAD + q * 8) =
                *(const float4*)(Wh + (size_t)(n0 + n) * DMODEL + k0 + q * 8);
            *(float4*)(Bl_ + n * HPAD + q * 8) =
                *(const float4*)(Wl + (size_t)(n0 + n) * DMODEL + k0 + q * 8);
        }
        __syncthreads();
        #pragma unroll
        for (int ks = 0; ks < 4; ++ks) {
            wmma::fragment<wmma::matrix_a, 16, 16, 16, __half, wmma::row_major> afh[2], afl[2];
            wmma::fragment<wmma::matrix_b, 16, 16, 16, __half, wmma::col_major> bfh[2], bfl[2];
            #pragma unroll
            for (int mi = 0; mi < 2; ++mi) {
                wmma::load_matrix_sync(afh[mi], Ah_ + (wm * 32 + mi * 16) * HPAD + ks * 16, HPAD);
                wmma::load_matrix_sync(afl[mi], Al_ + (wm * 32 + mi * 16) * HPAD + ks * 16, HPAD);
            }
            #pragma unroll
            for (int ni = 0; ni < 2; ++ni) {
                wmma::load_matrix_sync(bfh[ni], Bh_ + (wn * 32 + ni * 16) * HPAD + ks * 16, HPAD);
                wmma::load_matrix_sync(bfl[ni], Bl_ + (wn * 32 + ni * 16) * HPAD + ks * 16, HPAD);
            }
            #pragma unroll
            for (int mi = 0; mi < 2; ++mi)
                #pragma unroll
                for (int ni = 0; ni < 2; ++ni) {
                    wmma::mma_sync(Cc[mi][ni], afh[mi], bfh[ni], Cc[mi][ni]);
                    wmma::mma_sync(Cc[mi][ni], afh[mi], bfl[ni], Cc[mi][ni]);
                    wmma::mma_sync(Cc[mi][ni], afl[mi], bfh[ni], Cc[mi][ni]);
                }
        }
        __syncthreads();
    }

    float* Cb = (float*)sh;
    #pragma unroll
    for (int mi = 0; mi < 2; ++mi)
        #pragma unroll
        for (int ni = 0; ni < 2; ++ni)
            wmma::store_matrix_sync(Cb + (wm * 32 + mi * 16) * EPAD + wn * 32 + ni * 16,
                                    Cc[mi][ni], EPAD, wmma::mem_row_major);
    __syncthreads();
    const int r = tid >> 1;
    const int cc = (tid & 1) * 32;
    const int m = m0 + r;
    __half* ohr = Oh + (size_t)m * DMODEL + n0 + cc;
    __half* olr = Ol + (size_t)m * DMODEL + n0 + cc;
    #pragma unroll
    for (int q = 0; q < 8; ++q) {
        float4 cv = *(const float4*)(Cb + r * EPAD + cc + q * 4);
        float4 bb = *(const float4*)(bias + n0 + cc + q * 4);
        __half h[4], l[4];
        split_h(cv.x + bb.x, h[0], l[0]); split_h(cv.y + bb.y, h[1], l[1]);
        split_h(cv.z + bb.z, h[2], l[2]); split_h(cv.w + bb.w, h[3], l[3]);
        *(ulonglong1*)(ohr + q * 4) = *(ulonglong1*)h;
        *(ulonglong1*)(olr + q * 4) = *(ulonglong1*)l;
    }
}

// ---------------- proj h3 (N=80 predicated) ----------------
__global__ void __launch_bounds__(256, 2) k_proj_h3(
    const __half* __restrict__ Ahg, const __half* __restrict__ Alg,
    const __half* __restrict__ Wh, const __half* __restrict__ Wl,
    const float* __restrict__ bias, float* __restrict__ out)
{
    extern __shared__ __align__(16) __half sh[];
    __half* Ah_ = sh;
    __half* Al_ = sh + 128 * HPAD;
    __half* Bh_ = sh + 256 * HPAD;
    __half* Bl_ = sh + 320 * HPAD;
    const int tid = threadIdx.x;
    const int wid = tid >> 5;
    const int m0 = blockIdx.x * 128;
    const int n0 = blockIdx.y * 64;
    const int wm = wid & 3;
    const int wn = wid >> 2;

    wmma::fragment<wmma::accumulator, 16, 16, 16, float> Cc[2][2];
    #pragma unroll
    for (int i = 0; i < 2; ++i)
        #pragma unroll
        for (int j = 0; j < 2; ++j) wmma::fill_fragment(Cc[i][j], 0.0f);

    for (int c = 0; c < 4; ++c) {
        const int k0 = c * 64;
        #pragma unroll
        for (int i = 0; i < 4; ++i) {
            int e = tid + i * 256;
            int r = e >> 3, q = e & 7;
            *(float4*)(Ah_ + r * HPAD + q * 8) =
                *(const float4*)(Ahg + (size_t)(m0 + r) * DMODEL + k0 + q * 8);
            *(float4*)(Al_ + r * HPAD + q * 8) =
                *(const float4*)(Alg + (size_t)(m0 + r) * DMODEL + k0 + q * 8);
        }
        #pragma unroll
        for (int i = 0; i < 2; ++i) {
            int e = tid + i * 256;
            int n = e >> 3, q = e & 7;
            int row = n0 + n;
            float4 vh = make_float4(0.f, 0.f, 0.f, 0.f);
            float4 vl = vh;
            if (row < INDIM) {
                vh = *(const float4*)(Wh + (size_t)row * DMODEL + k0 + q * 8);
                vl = *(const float4*)(Wl + (size_t)row * DMODEL + k0 + q * 8);
            }
            *(float4*)(Bh_ + n * HPAD + q * 8) = vh;
            *(float4*)(Bl_ + n * HPAD + q * 8) = vl;
        }
        __syncthreads();
        #pragma unroll
        for (int ks = 0; ks < 4; ++ks) {
            wmma::fragment<wmma::matrix_a, 16, 16, 16, __half, wmma::row_major> afh[2], afl[2];
            wmma::fragment<wmma::matrix_b, 16, 16, 16, __half, wmma::col_major> bfh[2], bfl[2];
            #pragma unroll
            for (int mi = 0; mi < 2; ++mi) {
                wmma::load_matrix_sync(afh[mi], Ah_ + (wm * 32 + mi * 16) * HPAD + ks * 16, HPAD);
                wmma::load_matrix_sync(afl[mi], Al_ + (wm * 32 + mi * 16) * HPAD + ks * 16, HPAD);
            }
            #pragma unroll
            for (int ni = 0; ni < 2; ++ni) {
                wmma::load_matrix_sync(bfh[ni], Bh_ + (wn * 32 + ni * 16) * HPAD + ks * 16, HPAD);
                wmma::load_matrix_sync(bfl[ni], Bl_ + (wn * 32 + ni * 16) * HPAD + ks * 16, HPAD);
            }
            #pragma unroll
            for (int mi = 0; mi < 2; ++mi)
                #pragma unroll
                for (int ni = 0; ni < 2; ++ni) {
                    wmma::mma_sync(Cc[mi][ni], afh[mi], bfh[ni], Cc[mi][ni]);
                    wmma::mma_sync(Cc[mi][ni], afh[mi], bfl[ni], Cc[mi][ni]);
                    wmma::mma_sync(Cc[mi][ni], afl[mi], bfh[ni], Cc[mi][ni]);
                }
        }
        __syncthreads();
    }

    float* Cb = (float*)sh;
    #pragma unroll
    for (int mi = 0; mi < 2; ++mi)
        #pragma unroll
        for (int ni = 0; ni < 2; ++ni)
            wmma::store_matrix_sync(Cb + (wm * 32 + mi * 16) * EPAD + wn * 32 + ni * 16,
                                    Cc[mi][ni], EPAD, wmma::mem_row_major);
    __syncthreads();
    const int r = tid >> 1;
    const int cc = (tid & 1) * 32;
    const int m = m0 + r;
    #pragma unroll
    for (int q = 0; q < 8; ++q) {
        int col = n0 + cc + q * 4;
        if (col < INDIM) {
            float4 cv = *(const float4*)(Cb + r * EPAD + cc + q * 4);
            float4 bb = *(const float4*)(bias + col);
            *(float4*)(out + (size_t)m * INDIM + col) =
                make_float4(cv.x + bb.x, cv.y + bb.y, cv.z + bb.z, cv.w + bb.w);
        }
    }
}

// ---------------- K1: x = shift_right(mel @ W_lin^T + b_lin); also fp16 hi copy ----------------
__global__ void __launch_bounds__(256) k_lin_shift(
    const float* __restrict__ mel, const float* __restrict__ W,
    const float* __restrict__ bias, float* __restrict__ out,
    __half* __restrict__ outH)
{
    __shared__ float As[16][128];
    __shared__ float Bs[16][64];
    const int tid = threadIdx.x;
    const int m0 = blockIdx.x * 128;
    const int n0 = blockIdx.y * 64;
    const int tx = tid & 15, ty = tid >> 4;
    u64 acc[4][4];
    #pragma unroll
    for (int i = 0; i < 4; ++i)
        #pragma unroll
        for (int j = 0; j < 4; ++j) acc[i][j] = 0ULL;

    for (int k0 = 0; k0 < INDIM; k0 += 16) {
        #pragma unroll
        for (int i = 0; i < 2; ++i) {
            int s = tid + i * 256;
            int r = s >> 2, kq = (s & 3) << 2;
            int m = m0 + r;
            int t = m & (TDEC - 1);
            float4 v = make_float4(0.f, 0.f, 0.f, 0.f);
            if (t > 0) v = *(const float4*)(mel + (size_t)(m - 1) * INDIM + k0 + kq);
            As[kq + 0][r] = v.x; As[kq + 1][r] = v.y; As[kq + 2][r] = v.z; As[kq + 3][r] = v.w;
        }
        {
            int n = tid >> 2, kq = (tid & 3) << 2;
            float4 v = *(const float4*)(W + (size_t)(n0 + n) * INDIM + k0 + kq);
            Bs[kq + 0][n] = v.x; Bs[kq + 1][n] = v.y; Bs[kq + 2][n] = v.z; Bs[kq + 3][n] = v.w;
        }
        __syncthreads();
        #pragma unroll
        for (int k = 0; k < 16; ++k) {
            ulonglong2 aa0 = *(const ulonglong2*)&As[k][ty * 8];
            ulonglong2 aa1 = *(const ulonglong2*)&As[k][ty * 8 + 4];
            float4 br = *(const float4*)&Bs[k][tx * 4];
            u64 b0 = pack_dup(br.x), b1 = pack_dup(br.y), b2 = pack_dup(br.z), b3 = pack_dup(br.w);
            ffma2(acc[0][0], aa0.x, b0); ffma2(acc[0][1], aa0.x, b1);
            ffma2(acc[0][2], aa0.x, b2); ffma2(acc[0][3], aa0.x, b3);
            ffma2(acc[1][0], aa0.y, b0); ffma2(acc[1][1], aa0.y, b1);
            ffma2(acc[1][2], aa0.y, b2); ffma2(acc[1][3], aa0.y, b3);
            ffma2(acc[2][0], aa1.x, b0); ffma2(acc[2][1], aa1.x, b1);
            ffma2(acc[2][2], aa1.x, b2); ffma2(acc[2][3], aa1.x, b3);
            ffma2(acc[3][0], aa1.y, b0); ffma2(acc[3][1], aa1.y, b1);
            ffma2(acc[3][2], aa1.y, b2); ffma2(acc[3][3], aa1.y, b3);
        }
        __syncthreads();
    }
    float4 bb = *(const float4*)(bias + n0 + tx * 4);
    #pragma unroll
    for (int i2 = 0; i2 < 4; ++i2) {
        float2 c0 = unpk(acc[i2][0]), c1 = unpk(acc[i2][1]);
        float2 c2 = unpk(acc[i2][2]), c3 = unpk(acc[i2][3]);
        int m = m0 + ty * 8 + 2 * i2;
        #pragma unroll
        for (int h = 0; h < 2; ++h) {
            int mm = m + h;
            int t = mm & (TDEC - 1);
            float4 o;
            if (t == 0) o = make_float4(0.f, 0.f, 0.f, 0.f);
            else if (h == 0)
                o = make_float4(c0.x + bb.x, c1.x + bb.y, c2.x + bb.z, c3.x + bb.w);
            else
                o = make_float4(c0.y + bb.x, c1.y + bb.y, c2.y + bb.z, c3.y + bb.w);
            *(float4*)(out + (size_t)mm * DMODEL + n0 + tx * 4) = o;
            __half* hp = outH + (size_t)mm * DMODEL + n0 + tx * 4;
            *(__half2*)(hp)     = __floats2half2_rn(o.x, o.y);
            *(__half2*)(hp + 2) = __floats2half2_rn(o.z, o.w);
        }
    }
}

// ---------------- launch ----------------
extern "C" void kernel_launch(void* const* d_in, const int* in_sizes, int n_in,
                              void* d_out, int out_size)
{
    (void)in_sizes; (void)n_in; (void)out_size;
    const float* enc   = (const float*)d_in[0];
    const float* first = (const float*)d_in[1];
    const float* mel   = (const float*)d_in[2];
    const float* W_lin = (const float*)d_in[3];
    const float* b_lin = (const float*)d_in[4];
    const float* cw0   = (const float*)d_in[5];
    const float* cb0   = (const float*)d_in[6];
    const float* cw1   = (const float*)d_in[7];
    const float* cb1   = (const float*)d_in[8];
    const float* W_att = (const float*)d_in[9];
    const float* b_att = (const float*)d_in[10];
    const float* W_prj = (const float*)d_in[11];
    const float* b_prj = (const float*)d_in[12];
    float* out = (float*)d_out;

    float *X, *H0, *H1, *S;
    __half *XH, *H0h, *H0l, *Qh, *Ql, *AHh, *AHl, *EHh, *EHl, *VHh, *VHl;
    __half *WbH0, *WbH1, *WAh, *WAl, *WPh, *WPl;
    cudaGetSymbolAddress((void**)&X,  g_X);
    cudaGetSymbolAddress((void**)&H0, g_H0);
    cudaGetSymbolAddress((void**)&H1, g_H1);
    cudaGetSymbolAddress((void**)&S,  g_S);
    cudaGetSymbolAddress((void**)&XH, g_XH);
    cudaGetSymbolAddress((void**)&H0h, g_H0h);
    cudaGetSymbolAddress((void**)&H0l, g_H0l);
    cudaGetSymbolAddress((void**)&Qh, g_Qh);
    cudaGetSymbolAddress((void**)&Ql, g_Ql);
    cudaGetSymbolAddress((void**)&AHh, g_AHh);
    cudaGetSymbolAddress((void**)&AHl, g_AHl);
    cudaGetSymbolAddress((void**)&EHh, g_EHh);
    cudaGetSymbolAddress((void**)&EHl, g_EHl);
    cudaGetSymbolAddress((void**)&VHh, g_VHh);
    cudaGetSymbolAddress((void**)&VHl, g_VHl);
    cudaGetSymbolAddress((void**)&WbH0, g_WbH0);
    cudaGetSymbolAddress((void**)&WbH1, g_WbH1);
    cudaGetSymbolAddress((void**)&WAh, g_WAh);
    cudaGetSymbolAddress((void**)&WAl, g_WAl);
    cudaGetSymbolAddress((void**)&WPh, g_WPh);
    cudaGetSymbolAddress((void**)&WPl, g_WPl);

    const int CONV_SMEM = SMH * 2;    // 36864 B
    const int H3_SMEM   = H3SM * 2;   // 55296 B
    const int SC_SMEM   = SCSM * 2;   // 73728 B
    const int CX_SMEM   = CXSM * 2;   // 71680 B
    cudaFuncSetAttribute(k_conv_wmma, cudaFuncAttributeMaxDynamicSharedMemorySize, CONV_SMEM);
    cudaFuncSetAttribute(k_scores_h3, cudaFuncAttributeMaxDynamicSharedMemorySize, SC_SMEM);
    cudaFuncSetAttribute(k_ctx_h3,    cudaFuncAttributeMaxDynamicSharedMemorySize, CX_SMEM);
    cudaFuncSetAttribute(k_qgemm_h3,  cudaFuncAttributeMaxDynamicSharedMemorySize, H3_SMEM);
    cudaFuncSetAttribute(k_proj_h3,   cudaFuncAttributeMaxDynamicSharedMemorySize, H3_SMEM);

    k_repack_nk<<<(C2 * DMODEL * 5 + 255) / 256, 256>>>(cw0, WbH0);
    k_repack_nk<<<(C2 * DMODEL * 5 + 255) / 256, 256>>>(cw1, WbH1);
    k_prep_enc<<<(BDIM * TENC * DMODEL / 4) / 256, 256>>>(enc, first, EHh, EHl, VHh, VHl);
    k_split<<<(DMODEL * DMODEL / 4) / 256, 256>>>(W_att, WAh, WAl);
    k_split<<<(INDIM * DMODEL / 4) / 256, 256>>>(W_prj, WPh, WPl);
    k_lin_shift<<<dim3(MTOT / 128, DMODEL / 64), 256>>>(mel, W_lin, b_lin, X, XH);
    k_conv_wmma<<<dim3(MTOT / 128, DMODEL / 64), 256, CONV_SMEM>>>(
        X, XH, WbH0, cb0, H0, H0h, H0l, 1);
    k_qgemm_h3<<<dim3(MTOT / 128, DMODEL / 64), 256, H3_SMEM>>>(
        H0h, H0l, WAh, WAl, b_att, Qh, Ql);
    k_scores_h3<<<dim3(TDEC / 128, TENC / 128, BDIM), 256, SC_SMEM>>>(Qh, Ql, EHh, EHl, S);
    k_softmax<<<MTOT / 2, 256>>>(S, AHh, AHl);
    k_ctx_h3<<<dim3(TDEC / 128, DMODEL / 128, BDIM), 256, CX_SMEM>>>(
        AHh, AHl, VHh, VHl, H0, H1, XH);
    k_conv_wmma<<<dim3(MTOT / 128, DMODEL / 64), 256, CONV_SMEM>>>(
        H1, XH, WbH1, cb1, X, H0h, H0l, 0);
    k_proj_h3<<<dim3(MTOT / 128, 2), 256, H3_SMEM>>>(H0h, H0l, WPh, WPl, b_prj, out);
}